// round 1
// baseline (speedup 1.0000x reference)
#include <cuda_runtime.h>
#include <cuda_bf16.h>
#include <math.h>

// ----------------------------------------------------------------------------
// BahdanauAttentionAudio
//   B=32, T=2048, H=1024, U=1024, KN=32, kernel taps = 31
// Pipeline:
//   1) qproj[b,u]   = q[b]·W2_w[u] + W1_b[u] + W2_b[u]
//   2) locT[b,t,k]  = conv1d(prev_att)[b,k,t]  (stored t-major for GEMM)
//   3) score[b,t]   = V_b + sum_u V_w[u]*tanh( values[b,t]·W1_w[u]
//                                              + locT[b,t]·loc_proj_w[u]
//                                              + qproj[b,u] )
//   4) att[b,t]     = softmax_t(score[b,:])
//   5) ctx[b,h]     = sum_t att[b,t]*values[b,t,h]   (split-T partials + reduce)
// Output layout: [ ctx (32*1024) | att (32*2048) | score (32*2048) ]
// ----------------------------------------------------------------------------

#define B_   32
#define T_   2048
#define H_   1024
#define U_   1024
#define KN_  32
#define TAPS 31

// scratch (static device globals; no runtime allocation)
__device__ float g_qproj[B_ * U_];
__device__ float g_locT[(size_t)B_ * T_ * KN_];
__device__ float g_ctx_partial[B_ * 8 * H_];

// ---------------- packed f32x2 helpers --------------------------------------
__device__ __forceinline__ unsigned long long pk2(float x, float y) {
    unsigned long long r;
    asm("mov.b64 %0, {%1, %2};" : "=l"(r) : "f"(x), "f"(y));
    return r;
}
__device__ __forceinline__ float2 upk2(unsigned long long v) {
    float2 f;
    asm("mov.b64 {%0, %1}, %2;" : "=f"(f.x), "=f"(f.y) : "l"(v));
    return f;
}
__device__ __forceinline__ void fma2(unsigned long long& c,
                                     unsigned long long a,
                                     unsigned long long b) {
    asm("fma.rn.f32x2 %0, %1, %2, %0;" : "+l"(c) : "l"(a), "l"(b));
}

// ---------------- 1) query projection ---------------------------------------
// one warp per (b,u); coalesced over h
__global__ void qproj_kernel(const float* __restrict__ query,
                             const float* __restrict__ W2w,
                             const float* __restrict__ W1b,
                             const float* __restrict__ W2b) {
    int gw   = (blockIdx.x * blockDim.x + threadIdx.x) >> 5;
    int lane = threadIdx.x & 31;
    if (gw >= B_ * U_) return;
    int u = gw & (U_ - 1);
    int b = gw >> 10;
    const float* qrow = query + (size_t)b * H_;
    const float* wrow = W2w + (size_t)u * H_;
    float acc = 0.f;
#pragma unroll 4
    for (int h = lane; h < H_; h += 32) acc += qrow[h] * wrow[h];
#pragma unroll
    for (int off = 16; off > 0; off >>= 1)
        acc += __shfl_xor_sync(0xffffffffu, acc, off);
    if (lane == 0) g_qproj[(size_t)b * U_ + u] = acc + W1b[u] + W2b[u];
}

// ---------------- 2) location conv (stores t-major) --------------------------
__global__ void loc_kernel(const float* __restrict__ prev_att,
                           const float* __restrict__ conv_w) {
    int b  = blockIdx.y;
    int t0 = blockIdx.x * 256;
    int tid = threadIdx.x;
    __shared__ float pa[256 + TAPS - 1];
    __shared__ float w[KN_][TAPS];
    for (int i = tid; i < 256 + TAPS - 1; i += 256) {
        int t = t0 - (TAPS / 2) + i;
        pa[i] = (t >= 0 && t < T_) ? prev_att[(size_t)b * T_ + t] : 0.f;
    }
    for (int i = tid; i < KN_ * TAPS; i += 256) w[i / TAPS][i % TAPS] = conv_w[i];
    __syncthreads();
    int t = t0 + tid;
    float* out = g_locT + ((size_t)b * T_ + t) * KN_;
#pragma unroll 4
    for (int k = 0; k < KN_; k++) {
        float a = 0.f;
#pragma unroll
        for (int j = 0; j < TAPS; j++) a += w[k][j] * pa[tid + j];
        out[k] = a;
    }
}

// ---------------- 3) main score GEMM ----------------------------------------
#define BT 128
#define BU 128
#define KB 16

__global__ __launch_bounds__(256, 2)
void score_kernel(const float* __restrict__ values,
                  const float* __restrict__ W1w,
                  const float* __restrict__ LPw,
                  const float* __restrict__ Vw,
                  const float* __restrict__ Vb,
                  float* __restrict__ score_out) {
    const int b   = blockIdx.y;
    const int t0  = blockIdx.x * BT;
    const int tid = threadIdx.x;
    const int tx  = tid & 15;
    const int ty  = tid >> 4;

    __shared__ float As[BT][KB];        // row-major A tile
    __shared__ float Bs[KB][BU + 4];    // k-major B tile (padded)
    __shared__ float red[16][BT + 4];

    const float* Ab = values + ((size_t)b * T_ + t0) * H_;
    const float* Lb = g_locT + ((size_t)b * T_ + t0) * KN_;

    float rowsum[8];
#pragma unroll
    for (int i = 0; i < 8; i++) rowsum[i] = 0.f;

    const int ldr = tid >> 2;          // 0..63
    const int ldk = (tid & 3) * 4;     // 0,4,8,12

    for (int ub = 0; ub < U_ / BU; ub++) {
        const int u0 = ub * BU;
        unsigned long long c2[8][4];
#pragma unroll
        for (int i = 0; i < 8; i++)
#pragma unroll
            for (int j = 0; j < 4; j++) c2[i][j] = 0ull;

        for (int phase = 0; phase < 2; phase++) {
            const float* Ap; const float* Bp; int lda, ldb, Klen;
            if (phase == 0) { Ap = Ab; lda = H_;  Bp = W1w + (size_t)u0 * H_;  ldb = H_;  Klen = H_;  }
            else            { Ap = Lb; lda = KN_; Bp = LPw + (size_t)u0 * KN_; ldb = KN_; Klen = KN_; }

            for (int k0 = 0; k0 < Klen; k0 += KB) {
                __syncthreads();
                // load A tile (row-major, float4 stores — conflict free)
                float4 va0 = *(const float4*)&Ap[(size_t)ldr * lda + k0 + ldk];
                float4 va1 = *(const float4*)&Ap[(size_t)(ldr + 64) * lda + k0 + ldk];
                *(float4*)&As[ldr][ldk]      = va0;
                *(float4*)&As[ldr + 64][ldk] = va1;
                // load B tile, transpose into k-major
                float4 vb0 = *(const float4*)&Bp[(size_t)ldr * ldb + k0 + ldk];
                float4 vb1 = *(const float4*)&Bp[(size_t)(ldr + 64) * ldb + k0 + ldk];
                Bs[ldk + 0][ldr] = vb0.x; Bs[ldk + 1][ldr] = vb0.y;
                Bs[ldk + 2][ldr] = vb0.z; Bs[ldk + 3][ldr] = vb0.w;
                Bs[ldk + 0][ldr + 64] = vb1.x; Bs[ldk + 1][ldr + 64] = vb1.y;
                Bs[ldk + 2][ldr + 64] = vb1.z; Bs[ldk + 3][ldr + 64] = vb1.w;
                __syncthreads();

#pragma unroll
                for (int kk = 0; kk < KB; kk++) {
                    float a[8];
#pragma unroll
                    for (int i = 0; i < 4; i++) {
                        a[i]     = As[ty * 4 + i][kk];
                        a[i + 4] = As[64 + ty * 4 + i][kk];
                    }
                    float4 b0 = *(const float4*)&Bs[kk][tx * 4];
                    float4 b1 = *(const float4*)&Bs[kk][64 + tx * 4];
                    unsigned long long bp0 = pk2(b0.x, b0.y);
                    unsigned long long bp1 = pk2(b0.z, b0.w);
                    unsigned long long bp2 = pk2(b1.x, b1.y);
                    unsigned long long bp3 = pk2(b1.z, b1.w);
#pragma unroll
                    for (int i = 0; i < 8; i++) {
                        unsigned long long ap = pk2(a[i], a[i]);
                        fma2(c2[i][0], ap, bp0);
                        fma2(c2[i][1], ap, bp1);
                        fma2(c2[i][2], ap, bp2);
                        fma2(c2[i][3], ap, bp3);
                    }
                }
            }
        }

        // epilogue: + qproj, tanh, * V_w, accumulate row sums
        const float* qp = g_qproj + (size_t)b * U_ + u0;
        const float* vw = Vw + u0;
        const int cA = tx * 4;
        const int cB = 64 + tx * 4;
#pragma unroll
        for (int i = 0; i < 8; i++) {
#pragma unroll
            for (int j2 = 0; j2 < 4; j2++) {
                int col = (j2 < 2) ? (cA + j2 * 2) : (cB + (j2 - 2) * 2);
                float2 v = upk2(c2[i][j2]);
                float s0 = v.x + __ldg(&qp[col]);
                float s1 = v.y + __ldg(&qp[col + 1]);
                rowsum[i] += __ldg(&vw[col]) * tanhf(s0)
                           + __ldg(&vw[col + 1]) * tanhf(s1);
            }
        }
    }

    // cross-thread (tx) reduction per row
    __syncthreads();
#pragma unroll
    for (int i = 0; i < 8; i++) {
        int row = (i < 4) ? (ty * 4 + i) : (64 + ty * 4 + (i - 4));
        red[tx][row] = rowsum[i];
    }
    __syncthreads();
    if (tid < BT) {
        float s = 0.f;
#pragma unroll
        for (int x = 0; x < 16; x++) s += red[x][tid];
        score_out[(size_t)b * T_ + t0 + tid] = s + __ldg(Vb);
    }
}

// ---------------- 4) softmax over T -----------------------------------------
__global__ void softmax_kernel(const float* __restrict__ score,
                               float* __restrict__ att) {
    int b = blockIdx.x;
    int tid = threadIdx.x;  // 256
    __shared__ float sm[256];
    const float* s = score + (size_t)b * T_;

    float m = -3.402823466e38f;
    for (int t = tid; t < T_; t += 256) m = fmaxf(m, s[t]);
    sm[tid] = m;
    __syncthreads();
    for (int off = 128; off > 0; off >>= 1) {
        if (tid < off) sm[tid] = fmaxf(sm[tid], sm[tid + off]);
        __syncthreads();
    }
    float M = sm[0];
    __syncthreads();

    float acc = 0.f;
    for (int t = tid; t < T_; t += 256) acc += expf(s[t] - M);
    sm[tid] = acc;
    __syncthreads();
    for (int off = 128; off > 0; off >>= 1) {
        if (tid < off) sm[tid] += sm[tid + off];
        __syncthreads();
    }
    float inv = 1.0f / sm[0];

    for (int t = tid; t < T_; t += 256)
        att[(size_t)b * T_ + t] = expf(s[t] - M) * inv;
}

// ---------------- 5) context: split-T partials then reduce -------------------
__global__ void ctx_partial_kernel(const float* __restrict__ values,
                                   const float* __restrict__ att) {
    int b = blockIdx.y;
    int sp = blockIdx.x;            // 0..7, 256 t each
    int tid = threadIdx.x;          // 256, each handles 4 h (float4)
    __shared__ float a[256];
    int t0 = sp * 256;
    a[tid] = att[(size_t)b * T_ + t0 + tid];
    __syncthreads();
    const float4* vp = (const float4*)(values + ((size_t)b * T_ + t0) * H_) + tid;
    float4 c = make_float4(0.f, 0.f, 0.f, 0.f);
#pragma unroll 4
    for (int t = 0; t < 256; t++) {
        float4 v = vp[(size_t)t * (H_ / 4)];
        float w = a[t];
        c.x += w * v.x; c.y += w * v.y; c.z += w * v.z; c.w += w * v.w;
    }
    ((float4*)(g_ctx_partial + ((size_t)b * 8 + sp) * H_))[tid] = c;
}

__global__ void ctx_reduce_kernel(float* __restrict__ ctx) {
    int idx = blockIdx.x * 256 + threadIdx.x;   // 0..32767
    int b = idx >> 10;
    int h = idx & (H_ - 1);
    float s = 0.f;
#pragma unroll
    for (int sp = 0; sp < 8; sp++)
        s += g_ctx_partial[((size_t)b * 8 + sp) * H_ + h];
    ctx[idx] = s;
}

// ---------------- launch ------------------------------------------------------
extern "C" void kernel_launch(void* const* d_in, const int* in_sizes, int n_in,
                              void* d_out, int out_size) {
    const float* query    = (const float*)d_in[0];
    const float* values   = (const float*)d_in[1];
    const float* prev_att = (const float*)d_in[2];
    const float* W1w      = (const float*)d_in[3];
    const float* W1b      = (const float*)d_in[4];
    const float* W2w      = (const float*)d_in[5];
    const float* W2b      = (const float*)d_in[6];
    const float* Vw       = (const float*)d_in[7];
    const float* Vb       = (const float*)d_in[8];
    const float* conv_w   = (const float*)d_in[9];
    const float* LPw      = (const float*)d_in[10];

    float* out   = (float*)d_out;
    float* ctx   = out;                       // 32*1024
    float* att   = out + B_ * H_;             // 32*2048
    float* score = out + B_ * H_ + B_ * T_;   // 32*2048

    // 1) qproj: 32768 warps
    qproj_kernel<<<(B_ * U_ * 32 + 255) / 256, 256>>>(query, W2w, W1b, W2b);
    // 2) location conv
    {
        dim3 g(T_ / 256, B_);
        loc_kernel<<<g, 256>>>(prev_att, conv_w);
    }
    // 3) score GEMM
    {
        dim3 g(T_ / BT, B_);
        score_kernel<<<g, 256>>>(values, W1w, LPw, Vw, Vb, score);
    }
    // 4) softmax
    softmax_kernel<<<B_, 256>>>(score, att);
    // 5) context
    {
        dim3 g(8, B_);
        ctx_partial_kernel<<<g, 256>>>(values, att);
        ctx_reduce_kernel<<<B_ * H_ / 256, 256>>>(ctx);
    }
}

// round 3
// speedup vs baseline: 2.8313x; 2.8313x over previous
#include <cuda_runtime.h>
#include <cuda_bf16.h>
#include <cstdint>
#include <math.h>

// ----------------------------------------------------------------------------
// BahdanauAttentionAudio — mma.sync (HMMA bf16 split) score GEMM
//   B=32, T=2048, H=1024, U=1024, KN=32
// Output layout: [ ctx (32*1024) | att (32*2048) | score (32*2048) ]
// ----------------------------------------------------------------------------

#define B_   32
#define T_   2048
#define H_   1024
#define U_   1024
#define KN_  32
#define TAPS 31
#define NCH  33            // 32 chunks of H + 1 loc chunk (K=32 each)

// scratch (static device globals)
// packed tile format: per (chunk c, row r): 128 bytes =
//   granules 0..3 : 32 hi bf16 (k = c*32 .. c*32+31)
//   granules 4..7 : 32 lo bf16
// granule g stored at byte offset ((g ^ (r & 7)) * 16)  (pre-swizzled SW128)
__device__ __align__(128) uint4 g_vpk[(size_t)B_ * NCH * T_ * 8];   // [b][c][t][8]
__device__ __align__(128) uint4 g_wpk[(size_t)NCH * U_ * 8];        // [c][u][8]
__device__ __align__(16)  float g_qproj[B_ * U_];
__device__ __align__(16)  float g_part[8 * B_ * T_];
__device__ __align__(16)  float g_ctx_partial[B_ * 8 * H_];

// ---------------- helpers ----------------------------------------------------
__device__ __forceinline__ uint32_t smem_to_u32(const void* p) {
    uint32_t a;
    asm("{ .reg .u64 t; cvta.to.shared.u64 t, %1; cvt.u32.u64 %0, t; }"
        : "=r"(a) : "l"(p));
    return a;
}

__device__ __forceinline__ uint32_t pkbf(float a, float b) {
    __nv_bfloat162 t;
    t.x = __float2bfloat16(a);
    t.y = __float2bfloat16(b);
    return *reinterpret_cast<uint32_t*>(&t);
}

__device__ __forceinline__ void hilo8(const float* f, uint4& hi, uint4& lo) {
    float l[8];
#pragma unroll
    for (int i = 0; i < 8; i++)
        l[i] = f[i] - __bfloat162float(__float2bfloat16(f[i]));
    hi.x = pkbf(f[0], f[1]); hi.y = pkbf(f[2], f[3]);
    hi.z = pkbf(f[4], f[5]); hi.w = pkbf(f[6], f[7]);
    lo.x = pkbf(l[0], l[1]); lo.y = pkbf(l[2], l[3]);
    lo.z = pkbf(l[4], l[5]); lo.w = pkbf(l[6], l[7]);
}

#define MBARRIER_INIT(m, c) \
    asm volatile("mbarrier.init.shared.b64 [%0], %1;" \
                 :: "r"((uint32_t)(m)), "r"((uint32_t)(c)) : "memory")
#define MBARRIER_EXPECT_TX(m, n) \
    asm volatile("mbarrier.arrive.expect_tx.shared.b64 _, [%0], %1;" \
                 :: "r"((uint32_t)(m)), "r"((uint32_t)(n)) : "memory")

#define MBARRIER_WAIT_PARITY(mb, pp) do {                                     \
    uint32_t _m = (uint32_t)(mb), _p = (uint32_t)(pp), _d;                    \
    asm volatile(                                                             \
        "{\n\t.reg .pred p;\n\t"                                              \
        "mbarrier.try_wait.parity.acquire.cta.shared::cta.b64 p, [%1], %2;\n\t" \
        "selp.b32 %0, 1, 0, p;\n\t}"                                          \
        : "=r"(_d) : "r"(_m), "r"(_p) : "memory");                            \
    if (!_d) {                                                                \
        asm volatile(                                                         \
            "{\n\t.reg .pred P1;\n\t"                                         \
            "WL_%=:\n\t"                                                      \
            "mbarrier.try_wait.parity.acquire.cta.shared::cta.b64 P1, [%0], %1, 0x989680;\n\t" \
            "@P1 bra.uni WD_%=;\n\t"                                          \
            "bra.uni WL_%=;\n\t"                                              \
            "WD_%=:\n\t}"                                                     \
            :: "r"(_m), "r"(_p) : "memory");                                  \
    }                                                                         \
} while (0)

__device__ __forceinline__ void bulk_g2s(uint32_t dst, const void* src,
                                         uint32_t bytes, uint32_t mbar) {
    asm volatile(
        "cp.async.bulk.shared::cluster.global.mbarrier::complete_tx::bytes "
        "[%0], [%1], %2, [%3];"
        :: "r"(dst), "l"(src), "r"(bytes), "r"(mbar) : "memory");
}

__device__ __forceinline__ void ldsm4(uint32_t (&r)[4], uint32_t a) {
    asm volatile("ldmatrix.sync.aligned.m8n8.x4.shared.b16 {%0,%1,%2,%3}, [%4];"
                 : "=r"(r[0]), "=r"(r[1]), "=r"(r[2]), "=r"(r[3]) : "r"(a));
}

__device__ __forceinline__ void mma16816(float* c, const uint32_t* a,
                                         const uint32_t* b) {
    asm volatile(
        "mma.sync.aligned.m16n8k16.row.col.f32.bf16.bf16.f32 "
        "{%0,%1,%2,%3}, {%4,%5,%6,%7}, {%8,%9}, {%0,%1,%2,%3};"
        : "+f"(c[0]), "+f"(c[1]), "+f"(c[2]), "+f"(c[3])
        : "r"(a[0]), "r"(a[1]), "r"(a[2]), "r"(a[3]), "r"(b[0]), "r"(b[1]));
}

// ---------------- 1) query projection ---------------------------------------
__global__ void qproj_kernel(const float* __restrict__ query,
                             const float* __restrict__ W2w,
                             const float* __restrict__ W1b,
                             const float* __restrict__ W2b) {
    int gw   = (blockIdx.x * blockDim.x + threadIdx.x) >> 5;
    int lane = threadIdx.x & 31;
    if (gw >= B_ * U_) return;
    int u = gw & (U_ - 1);
    int b = gw >> 10;
    const float* qrow = query + (size_t)b * H_;
    const float* wrow = W2w + (size_t)u * H_;
    float acc = 0.f;
#pragma unroll 4
    for (int h = lane; h < H_; h += 32) acc += qrow[h] * wrow[h];
#pragma unroll
    for (int off = 16; off > 0; off >>= 1)
        acc += __shfl_xor_sync(0xffffffffu, acc, off);
    if (lane == 0) g_qproj[(size_t)b * U_ + u] = acc + W1b[u] + W2b[u];
}

// ---------------- 2a) pack values --------------------------------------------
__global__ void pack_values_kernel(const float* __restrict__ values) {
    int idx = blockIdx.x * 256 + threadIdx.x;     // ((b*32 + c)*2048 + t)
    int t  = idx & 2047;
    int bc = idx >> 11;
    int c  = bc & 31;
    int b  = bc >> 5;
    const float4* src = (const float4*)values + ((size_t)(b * 2048 + t) * 256 + c * 8);
    uint4* dst = g_vpk + ((size_t)((b * NCH + c) * 2048 + t) * 8);
    int r = t & 7;
    float f[8];
#pragma unroll
    for (int g = 0; g < 4; g++) {
        float4 v0 = __ldg(src + g * 2), v1 = __ldg(src + g * 2 + 1);
        f[0] = v0.x; f[1] = v0.y; f[2] = v0.z; f[3] = v0.w;
        f[4] = v1.x; f[5] = v1.y; f[6] = v1.z; f[7] = v1.w;
        uint4 hi, lo;
        hilo8(f, hi, lo);
        dst[g ^ r] = hi;
        dst[(g + 4) ^ r] = lo;
    }
}

// ---------------- 2b) pack W1_w ----------------------------------------------
__global__ void pack_w_kernel(const float* __restrict__ W1w) {
    int idx = blockIdx.x * 256 + threadIdx.x;     // c*1024 + u
    int u = idx & 1023;
    int c = idx >> 10;
    const float4* src = (const float4*)W1w + ((size_t)u * 256 + c * 8);
    uint4* dst = g_wpk + ((size_t)(c * U_ + u) * 8);
    int r = u & 7;
    float f[8];
#pragma unroll
    for (int g = 0; g < 4; g++) {
        float4 v0 = __ldg(src + g * 2), v1 = __ldg(src + g * 2 + 1);
        f[0] = v0.x; f[1] = v0.y; f[2] = v0.z; f[3] = v0.w;
        f[4] = v1.x; f[5] = v1.y; f[6] = v1.z; f[7] = v1.w;
        uint4 hi, lo;
        hilo8(f, hi, lo);
        dst[g ^ r] = hi;
        dst[(g + 4) ^ r] = lo;
    }
}

// ---------------- 2c) pack loc_proj_w (chunk 32 of W) ------------------------
__global__ void pack_lp_kernel(const float* __restrict__ LPw) {
    int u = blockIdx.x * 256 + threadIdx.x;       // 0..1023
    const float4* src = (const float4*)LPw + (size_t)u * 8;
    uint4* dst = g_wpk + ((size_t)(32 * U_ + u) * 8);
    int r = u & 7;
    float f[8];
#pragma unroll
    for (int g = 0; g < 4; g++) {
        float4 v0 = __ldg(src + g * 2), v1 = __ldg(src + g * 2 + 1);
        f[0] = v0.x; f[1] = v0.y; f[2] = v0.z; f[3] = v0.w;
        f[4] = v1.x; f[5] = v1.y; f[6] = v1.z; f[7] = v1.w;
        uint4 hi, lo;
        hilo8(f, hi, lo);
        dst[g ^ r] = hi;
        dst[(g + 4) ^ r] = lo;
    }
}

// ---------------- 2d) location conv + pack (chunk 32 of V) -------------------
__global__ void loc_pack_kernel(const float* __restrict__ prev_att,
                                const float* __restrict__ conv_w) {
    int b  = blockIdx.y;
    int t0 = blockIdx.x * 256;
    int tid = threadIdx.x;
    __shared__ float pa[256 + TAPS - 1];
    __shared__ float w[KN_][TAPS];
    for (int i = tid; i < 256 + TAPS - 1; i += 256) {
        int t = t0 - (TAPS / 2) + i;
        pa[i] = (t >= 0 && t < T_) ? prev_att[(size_t)b * T_ + t] : 0.f;
    }
    for (int i = tid; i < KN_ * TAPS; i += 256) w[i / TAPS][i % TAPS] = conv_w[i];
    __syncthreads();
    int t = t0 + tid;
    float a[KN_];
#pragma unroll 4
    for (int k = 0; k < KN_; k++) {
        float s = 0.f;
#pragma unroll
        for (int j = 0; j < TAPS; j++) s += w[k][j] * pa[tid + j];
        a[k] = s;
    }
    uint4* dst = g_vpk + ((size_t)((b * NCH + 32) * 2048 + t) * 8);
    int r = t & 7;
#pragma unroll
    for (int g = 0; g < 4; g++) {
        uint4 hi, lo;
        hilo8(a + g * 8, hi, lo);
        dst[g ^ r] = hi;
        dst[(g + 4) ^ r] = lo;
    }
}

// ---------------- 3) score GEMM via mma.sync ---------------------------------
// CTA: 128 t x 128 u, K = 33 chunks of 32. 4-stage cp.async.bulk pipeline.
#define STG_BYTES 32768      // A 16KB + B 16KB
#define OFF_MBAR  131072
#define OFF_QP    131136
#define OFF_VW    131648
#define OFF_RED   132160
#define SMEM_TOTAL 134272

__device__ __forceinline__ void issue_chunk(uint32_t sb, int s, int c,
                                            int b, int t0, int u0) {
    uint32_t mbar = sb + OFF_MBAR + s * 8;
    MBARRIER_EXPECT_TX(mbar, 32768u);
    const void* srcA = (const void*)(g_vpk + ((size_t)((b * NCH + c) * 2048 + t0) * 8));
    const void* srcB = (const void*)(g_wpk + ((size_t)(c * U_ + u0) * 8));
    bulk_g2s(sb + s * STG_BYTES,         srcA, 16384u, mbar);
    bulk_g2s(sb + s * STG_BYTES + 16384, srcB, 16384u, mbar);
}

__global__ __launch_bounds__(256, 1)
void score_mma_kernel(const float* __restrict__ Vw) {
    extern __shared__ char smem[];
    const uint32_t sb = smem_to_u32(smem);
    const int tid  = threadIdx.x;
    const int lane = tid & 31;
    const int wid  = tid >> 5;
    const int ut = blockIdx.x;          // 0..7  (u tile, fastest -> A L2 reuse)
    const int b  = blockIdx.y;          // 0..31
    const int tt = blockIdx.z;          // 0..15
    const int t0 = tt * 128, u0 = ut * 128;

    if (tid == 0) {
#pragma unroll
        for (int s = 0; s < 4; s++) MBARRIER_INIT(sb + OFF_MBAR + s * 8, 1);
    }
    __syncthreads();
    if (tid == 0) {
        for (int c = 0; c < 3; c++) issue_chunk(sb, c, c, b, t0, u0);
    }

    float* qp = (float*)(smem + OFF_QP);
    float* vw = (float*)(smem + OFF_VW);
    if (tid < 128)      qp[tid] = g_qproj[b * U_ + u0 + tid];
    else                vw[tid - 128] = __ldg(Vw + u0 + tid - 128);

    float acc[16][4];
#pragma unroll
    for (int i = 0; i < 16; i++)
#pragma unroll
        for (int j = 0; j < 4; j++) acc[i][j] = 0.f;

    const int wm = wid & 1;             // t half (rows wm*64..+63)
    const int wn = wid >> 1;            // u quarter (cols wn*32..+31)
    const int rowA = lane & 15;
    const int ka   = lane >> 4;                        // k8-half for A
    const int rowB = (lane & 7) | ((lane >> 4) << 3);
    const int kb   = (lane >> 3) & 1;                  // k8-half for B
    const uint32_t aOff = (uint32_t)((wm * 64 + rowA) * 128);
    const uint32_t bOff = (uint32_t)(16384 + (wn * 32 + rowB) * 128);

    for (int c = 0; c < NCH; c++) {
        const int s = c & 3;
        MBARRIER_WAIT_PARITY(sb + OFF_MBAR + s * 8, (c >> 2) & 1);
        const uint32_t stg = sb + s * STG_BYTES;
        const uint32_t aB = stg + aOff;
        const uint32_t bB = stg + bOff;
#pragma unroll
        for (int ks = 0; ks < 2; ks++) {
            const int gA = ks * 2 + ka;
            const int gB = ks * 2 + kb;
            const uint32_t swA  = (uint32_t)(((gA     ) ^ (rowA & 7)) << 4);
            const uint32_t swAl = (uint32_t)(((gA + 4) ^ (rowA & 7)) << 4);
            const uint32_t swB  = (uint32_t)(((gB     ) ^ (rowB & 7)) << 4);
            const uint32_t swBl = (uint32_t)(((gB + 4) ^ (rowB & 7)) << 4);

            uint32_t ah[4][4], bh[4][2], bl[4][2], al[4][4], tmp[4];
#pragma unroll
            for (int mt = 0; mt < 4; mt++) ldsm4(ah[mt], aB + mt * 2048 + swA);
            ldsm4(tmp, bB + swB);
            bh[0][0] = tmp[0]; bh[0][1] = tmp[1]; bh[1][0] = tmp[2]; bh[1][1] = tmp[3];
            ldsm4(tmp, bB + 2048 + swB);
            bh[2][0] = tmp[0]; bh[2][1] = tmp[1]; bh[3][0] = tmp[2]; bh[3][1] = tmp[3];
#pragma unroll
            for (int mt = 0; mt < 4; mt++)
#pragma unroll
                for (int nt = 0; nt < 4; nt++)
                    mma16816(acc[mt * 4 + nt], ah[mt], bh[nt]);

            ldsm4(tmp, bB + swBl);
            bl[0][0] = tmp[0]; bl[0][1] = tmp[1]; bl[1][0] = tmp[2]; bl[1][1] = tmp[3];
            ldsm4(tmp, bB + 2048 + swBl);
            bl[2][0] = tmp[0]; bl[2][1] = tmp[1]; bl[3][0] = tmp[2]; bl[3][1] = tmp[3];
#pragma unroll
            for (int mt = 0; mt < 4; mt++)
#pragma unroll
                for (int nt = 0; nt < 4; nt++)
                    mma16816(acc[mt * 4 + nt], ah[mt], bl[nt]);

#pragma unroll
            for (int mt = 0; mt < 4; mt++) ldsm4(al[mt], aB + mt * 2048 + swAl);
#pragma unroll
            for (int mt = 0; mt < 4; mt++)
#pragma unroll
                for (int nt = 0; nt < 4; nt++)
                    mma16816(acc[mt * 4 + nt], al[mt], bh[nt]);
        }
        __syncthreads();
        if (tid == 0 && c + 3 < NCH) issue_chunk(sb, (c + 3) & 3, c + 3, b, t0, u0);
    }

    // epilogue: s = acc + qp[u]; rowsum += vw[u] * tanh(s)
    float rs[4][2];
#pragma unroll
    for (int mt = 0; mt < 4; mt++) { rs[mt][0] = 0.f; rs[mt][1] = 0.f; }
#pragma unroll
    for (int mt = 0; mt < 4; mt++) {
#pragma unroll
        for (int nt = 0; nt < 4; nt++) {
            int uc = wn * 32 + nt * 8 + ((lane & 3) << 1);
            float q0 = qp[uc], q1 = qp[uc + 1];
            float v0 = vw[uc], v1 = vw[uc + 1];
            float* a = acc[mt * 4 + nt];
            rs[mt][0] += v0 * tanhf(a[0] + q0) + v1 * tanhf(a[1] + q1);
            rs[mt][1] += v0 * tanhf(a[2] + q0) + v1 * tanhf(a[3] + q1);
        }
#pragma unroll
        for (int off = 1; off <= 2; off <<= 1) {
            rs[mt][0] += __shfl_xor_sync(0xffffffffu, rs[mt][0], off);
            rs[mt][1] += __shfl_xor_sync(0xffffffffu, rs[mt][1], off);
        }
    }
    float* red = (float*)(smem + OFF_RED);
    if ((lane & 3) == 0) {
#pragma unroll
        for (int mt = 0; mt < 4; mt++) {
            int r = wm * 64 + mt * 16 + (lane >> 2);
            red[wn * 128 + r]     = rs[mt][0];
            red[wn * 128 + r + 8] = rs[mt][1];
        }
    }
    __syncthreads();
    if (tid < 128) {
        float s = red[tid] + red[128 + tid] + red[256 + tid] + red[384 + tid];
        g_part[(size_t)ut * (B_ * T_) + b * T_ + t0 + tid] = s;
    }
}

// ---------------- 4) combine + softmax ---------------------------------------
__global__ void softmax_kernel(const float* __restrict__ Vb,
                               float* __restrict__ score,
                               float* __restrict__ att) {
    int b = blockIdx.x;
    int tid = threadIdx.x;  // 256
    __shared__ float sm[256];
    const float vb = __ldg(Vb);

    float v[8];
    float m = -3.402823466e38f;
#pragma unroll
    for (int i = 0; i < 8; i++) {
        int t = tid + i * 256;
        float s = vb;
#pragma unroll
        for (int z = 0; z < 8; z++) s += g_part[(size_t)z * (B_ * T_) + b * T_ + t];
        v[i] = s;
        score[(size_t)b * T_ + t] = s;
        m = fmaxf(m, s);
    }
    sm[tid] = m;
    __syncthreads();
    for (int off = 128; off > 0; off >>= 1) {
        if (tid < off) sm[tid] = fmaxf(sm[tid], sm[tid + off]);
        __syncthreads();
    }
    float M = sm[0];
    __syncthreads();

    float acc = 0.f;
#pragma unroll
    for (int i = 0; i < 8; i++) { v[i] = expf(v[i] - M); acc += v[i]; }
    sm[tid] = acc;
    __syncthreads();
    for (int off = 128; off > 0; off >>= 1) {
        if (tid < off) sm[tid] += sm[tid + off];
        __syncthreads();
    }
    float inv = 1.0f / sm[0];
#pragma unroll
    for (int i = 0; i < 8; i++)
        att[(size_t)b * T_ + tid + i * 256] = v[i] * inv;
}

// ---------------- 5) context --------------------------------------------------
__global__ void ctx_partial_kernel(const float* __restrict__ values,
                                   const float* __restrict__ att) {
    int b = blockIdx.y;
    int sp = blockIdx.x;
    int tid = threadIdx.x;
    __shared__ float a[256];
    int t0 = sp * 256;
    a[tid] = att[(size_t)b * T_ + t0 + tid];
    __syncthreads();
    const float4* vp = (const float4*)(values + ((size_t)b * T_ + t0) * H_) + tid;
    float4 c = make_float4(0.f, 0.f, 0.f, 0.f);
#pragma unroll 4
    for (int t = 0; t < 256; t++) {
        float4 vv = vp[(size_t)t * (H_ / 4)];
        float w = a[t];
        c.x += w * vv.x; c.y += w * vv.y; c.z += w * vv.z; c.w += w * vv.w;
    }
    ((float4*)(g_ctx_partial + ((size_t)b * 8 + sp) * H_))[tid] = c;
}

__global__ void ctx_reduce_kernel(float* __restrict__ ctx) {
    int idx = blockIdx.x * 256 + threadIdx.x;
    int b = idx >> 10;
    int h = idx & (H_ - 1);
    float s = 0.f;
#pragma unroll
    for (int sp = 0; sp < 8; sp++)
        s += g_ctx_partial[((size_t)b * 8 + sp) * H_ + h];
    ctx[idx] = s;
}

// ---------------- launch ------------------------------------------------------
extern "C" void kernel_launch(void* const* d_in, const int* in_sizes, int n_in,
                              void* d_out, int out_size) {
    const float* query    = (const float*)d_in[0];
    const float* values   = (const float*)d_in[1];
    const float* prev_att = (const float*)d_in[2];
    const float* W1w      = (const float*)d_in[3];
    const float* W1b      = (const float*)d_in[4];
    const float* W2w      = (const float*)d_in[5];
    const float* W2b      = (const float*)d_in[6];
    const float* Vw       = (const float*)d_in[7];
    const float* Vb       = (const float*)d_in[8];
    const float* conv_w   = (const float*)d_in[9];
    const float* LPw      = (const float*)d_in[10];

    float* out   = (float*)d_out;
    float* ctx   = out;
    float* att   = out + B_ * H_;
    float* score = out + B_ * H_ + B_ * T_;

    cudaFuncSetAttribute(score_mma_kernel,
                         cudaFuncAttributeMaxDynamicSharedMemorySize, SMEM_TOTAL);

    qproj_kernel<<<(B_ * U_ * 32 + 255) / 256, 256>>>(query, W2w, W1b, W2b);
    pack_w_kernel<<<(32 * U_) / 256, 256>>>(W1w);
    pack_lp_kernel<<<U_ / 256, 256>>>(LPw);
    pack_values_kernel<<<(B_ * 32 * T_) / 256, 256>>>(values);
    {
        dim3 g(T_ / 256, B_);
        loc_pack_kernel<<<g, 256>>>(prev_att, conv_w);
    }
    {
        dim3 g(8, B_, 16);   // x = u-tile (fastest, shares A tile), y = b, z = t-tile
        score_mma_kernel<<<g, 256, SMEM_TOTAL>>>(Vw);
    }
    softmax_kernel<<<B_, 256>>>(Vb, score, att);
    {
        dim3 g(8, B_);
        ctx_partial_kernel<<<g, 256>>>(values, att);
        ctx_reduce_kernel<<<B_ * H_ / 256, 256>>>(ctx);
    }
}

// round 4
// speedup vs baseline: 4.2436x; 1.4988x over previous
#include <cuda_runtime.h>
#include <cuda_fp16.h>
#include <cstdint>
#include <math.h>

// ----------------------------------------------------------------------------
// BahdanauAttentionAudio — HMMA fp16 2-term split score GEMM
//   B=32, T=2048, H=1024, U=1024, KN=32
//   score GEMM: C = A_fp16 · (Bhi + Blo)  (A exact-ish single fp16, B split)
// Output layout: [ ctx (32*1024) | att (32*2048) | score (32*2048) ]
// ----------------------------------------------------------------------------

#define B_   32
#define T_   2048
#define H_   1024
#define U_   1024
#define KN_  32
#define TAPS 31
#define NCH  17            // 16 chunks of H (K=64) + 1 loc chunk (K=32 pad 64)

// packed format: per (chunk c, row r): 128 bytes = 64 fp16 (k = c*64 .. +63)
// granule g (8 fp16 = 16B) stored at byte offset ((g ^ (r & 7)) * 16)
__device__ __align__(128) uint4 g_vpk[(size_t)B_ * NCH * T_ * 8];   // [b][c][t][8]
__device__ __align__(128) uint4 g_wpk[(size_t)2 * NCH * U_ * 8];    // [c*2+hl][u][8]
__device__ __align__(16)  float g_qproj[B_ * U_];
__device__ __align__(16)  float g_part[8 * B_ * T_];
__device__ __align__(16)  float g_ctx_partial[B_ * 8 * H_];

// ---------------- helpers ----------------------------------------------------
__device__ __forceinline__ uint32_t smem_to_u32(const void* p) {
    uint32_t a;
    asm("{ .reg .u64 t; cvta.to.shared.u64 t, %1; cvt.u32.u64 %0, t; }"
        : "=r"(a) : "l"(p));
    return a;
}

__device__ __forceinline__ uint32_t pkh(float a, float b) {
    __half2 h = __floats2half2_rn(a, b);
    return *reinterpret_cast<uint32_t*>(&h);
}

__device__ __forceinline__ uint4 pk8(const float* f) {
    uint4 r;
    r.x = pkh(f[0], f[1]); r.y = pkh(f[2], f[3]);
    r.z = pkh(f[4], f[5]); r.w = pkh(f[6], f[7]);
    return r;
}

#define MBARRIER_INIT(m, c) \
    asm volatile("mbarrier.init.shared.b64 [%0], %1;" \
                 :: "r"((uint32_t)(m)), "r"((uint32_t)(c)) : "memory")
#define MBARRIER_EXPECT_TX(m, n) \
    asm volatile("mbarrier.arrive.expect_tx.shared.b64 _, [%0], %1;" \
                 :: "r"((uint32_t)(m)), "r"((uint32_t)(n)) : "memory")

#define MBARRIER_WAIT_PARITY(mb, pp) do {                                     \
    uint32_t _m = (uint32_t)(mb), _p = (uint32_t)(pp), _d;                    \
    asm volatile(                                                             \
        "{\n\t.reg .pred p;\n\t"                                              \
        "mbarrier.try_wait.parity.acquire.cta.shared::cta.b64 p, [%1], %2;\n\t" \
        "selp.b32 %0, 1, 0, p;\n\t}"                                          \
        : "=r"(_d) : "r"(_m), "r"(_p) : "memory");                            \
    if (!_d) {                                                                \
        asm volatile(                                                         \
            "{\n\t.reg .pred P1;\n\t"                                         \
            "WL_%=:\n\t"                                                      \
            "mbarrier.try_wait.parity.acquire.cta.shared::cta.b64 P1, [%0], %1, 0x989680;\n\t" \
            "@P1 bra.uni WD_%=;\n\t"                                          \
            "bra.uni WL_%=;\n\t"                                              \
            "WD_%=:\n\t}"                                                     \
            :: "r"(_m), "r"(_p) : "memory");                                  \
    }                                                                         \
} while (0)

__device__ __forceinline__ void bulk_g2s(uint32_t dst, const void* src,
                                         uint32_t bytes, uint32_t mbar) {
    asm volatile(
        "cp.async.bulk.shared::cluster.global.mbarrier::complete_tx::bytes "
        "[%0], [%1], %2, [%3];"
        :: "r"(dst), "l"(src), "r"(bytes), "r"(mbar) : "memory");
}

__device__ __forceinline__ void ldsm4(uint32_t (&r)[4], uint32_t a) {
    asm volatile("ldmatrix.sync.aligned.m8n8.x4.shared.b16 {%0,%1,%2,%3}, [%4];"
                 : "=r"(r[0]), "=r"(r[1]), "=r"(r[2]), "=r"(r[3]) : "r"(a));
}

__device__ __forceinline__ void mma16816(float* c, const uint32_t* a,
                                         const uint32_t* b) {
    asm volatile(
        "mma.sync.aligned.m16n8k16.row.col.f32.f16.f16.f32 "
        "{%0,%1,%2,%3}, {%4,%5,%6,%7}, {%8,%9}, {%0,%1,%2,%3};"
        : "+f"(c[0]), "+f"(c[1]), "+f"(c[2]), "+f"(c[3])
        : "r"(a[0]), "r"(a[1]), "r"(a[2]), "r"(a[3]), "r"(b[0]), "r"(b[1]));
}

// ---------------- 1) query projection ---------------------------------------
__global__ void qproj_kernel(const float* __restrict__ query,
                             const float* __restrict__ W2w,
                             const float* __restrict__ W1b,
                             const float* __restrict__ W2b) {
    int gw   = (blockIdx.x * blockDim.x + threadIdx.x) >> 5;
    int lane = threadIdx.x & 31;
    if (gw >= B_ * U_) return;
    int u = gw & (U_ - 1);
    int b = gw >> 10;
    const float* qrow = query + (size_t)b * H_;
    const float* wrow = W2w + (size_t)u * H_;
    float acc = 0.f;
#pragma unroll 4
    for (int h = lane; h < H_; h += 32) acc += qrow[h] * wrow[h];
#pragma unroll
    for (int off = 16; off > 0; off >>= 1)
        acc += __shfl_xor_sync(0xffffffffu, acc, off);
    if (lane == 0) g_qproj[(size_t)b * U_ + u] = acc + W1b[u] + W2b[u];
}

// ---------------- 2a) pack values (fp16 single) -------------------------------
__global__ void pack_values_kernel(const float* __restrict__ values) {
    int idx = blockIdx.x * 256 + threadIdx.x;   // (b*16 + c)*2048 + t
    int t  = idx & 2047;
    int bc = idx >> 11;
    int c  = bc & 15;
    int b  = bc >> 4;
    const float4* src = (const float4*)(values + ((size_t)(b * 2048 + t) * 1024 + c * 64));
    uint4* dst = g_vpk + ((size_t)((b * NCH + c) * 2048 + t) * 8);
    int r = t & 7;
    float f[8];
#pragma unroll
    for (int g = 0; g < 8; g++) {
        float4 v0 = __ldg(src + g * 2), v1 = __ldg(src + g * 2 + 1);
        f[0] = v0.x; f[1] = v0.y; f[2] = v0.z; f[3] = v0.w;
        f[4] = v1.x; f[5] = v1.y; f[6] = v1.z; f[7] = v1.w;
        dst[g ^ r] = pk8(f);
    }
}

// ---------------- 2b) pack W1_w (fp16 hi/lo planes) ---------------------------
__global__ void pack_w_kernel(const float* __restrict__ W1w) {
    int idx = blockIdx.x * 256 + threadIdx.x;   // c*1024 + u  (c 0..15)
    int u = idx & 1023;
    int c = idx >> 10;
    const float4* src = (const float4*)(W1w + ((size_t)u * 1024 + c * 64));
    uint4* dhi = g_wpk + ((size_t)((c * 2 + 0) * U_ + u) * 8);
    uint4* dlo = g_wpk + ((size_t)((c * 2 + 1) * U_ + u) * 8);
    int r = u & 7;
    float f[8], fl[8];
#pragma unroll
    for (int g = 0; g < 8; g++) {
        float4 v0 = __ldg(src + g * 2), v1 = __ldg(src + g * 2 + 1);
        f[0] = v0.x; f[1] = v0.y; f[2] = v0.z; f[3] = v0.w;
        f[4] = v1.x; f[5] = v1.y; f[6] = v1.z; f[7] = v1.w;
        uint4 hi;
        __half hh[8];
#pragma unroll
        for (int i = 0; i < 8; i++) {
            hh[i] = __float2half_rn(f[i]);
            fl[i] = f[i] - __half2float(hh[i]);
        }
        hi.x = pkh(f[0], f[1]); hi.y = pkh(f[2], f[3]);
        hi.z = pkh(f[4], f[5]); hi.w = pkh(f[6], f[7]);
        dhi[g ^ r] = hi;
        dlo[g ^ r] = pk8(fl);
    }
}

// ---------------- 2c) pack loc_proj_w (chunk 16 of W) -------------------------
__global__ void pack_lp_kernel(const float* __restrict__ LPw) {
    int u = blockIdx.x * 256 + threadIdx.x;     // 0..1023
    const float4* src = (const float4*)(LPw + (size_t)u * 32);
    uint4* dhi = g_wpk + ((size_t)((16 * 2 + 0) * U_ + u) * 8);
    uint4* dlo = g_wpk + ((size_t)((16 * 2 + 1) * U_ + u) * 8);
    int r = u & 7;
    float f[8], fl[8];
    uint4 z = make_uint4(0, 0, 0, 0);
#pragma unroll
    for (int g = 0; g < 4; g++) {
        float4 v0 = __ldg(src + g * 2), v1 = __ldg(src + g * 2 + 1);
        f[0] = v0.x; f[1] = v0.y; f[2] = v0.z; f[3] = v0.w;
        f[4] = v1.x; f[5] = v1.y; f[6] = v1.z; f[7] = v1.w;
        uint4 hi;
        __half hh[8];
#pragma unroll
        for (int i = 0; i < 8; i++) {
            hh[i] = __float2half_rn(f[i]);
            fl[i] = f[i] - __half2float(hh[i]);
        }
        hi.x = pkh(f[0], f[1]); hi.y = pkh(f[2], f[3]);
        hi.z = pkh(f[4], f[5]); hi.w = pkh(f[6], f[7]);
        dhi[g ^ r] = hi;
        dlo[g ^ r] = pk8(fl);
    }
#pragma unroll
    for (int g = 4; g < 8; g++) { dhi[g ^ r] = z; dlo[g ^ r] = z; }
}

// ---------------- 2d) location conv + pack (chunk 16 of V) --------------------
__global__ void loc_pack_kernel(const float* __restrict__ prev_att,
                                const float* __restrict__ conv_w) {
    int b  = blockIdx.y;
    int t0 = blockIdx.x * 256;
    int tid = threadIdx.x;
    __shared__ float pa[256 + TAPS - 1];
    __shared__ float w[KN_][TAPS];
    for (int i = tid; i < 256 + TAPS - 1; i += 256) {
        int t = t0 - (TAPS / 2) + i;
        pa[i] = (t >= 0 && t < T_) ? prev_att[(size_t)b * T_ + t] : 0.f;
    }
    for (int i = tid; i < KN_ * TAPS; i += 256) w[i / TAPS][i % TAPS] = conv_w[i];
    __syncthreads();
    int t = t0 + tid;
    float a[KN_];
#pragma unroll 4
    for (int k = 0; k < KN_; k++) {
        float s = 0.f;
#pragma unroll
        for (int j = 0; j < TAPS; j++) s += w[k][j] * pa[tid + j];
        a[k] = s;
    }
    uint4* dst = g_vpk + ((size_t)((b * NCH + 16) * 2048 + t) * 8);
    int r = t & 7;
    uint4 z = make_uint4(0, 0, 0, 0);
#pragma unroll
    for (int g = 0; g < 4; g++) dst[g ^ r] = pk8(a + g * 8);
#pragma unroll
    for (int g = 4; g < 8; g++) dst[g ^ r] = z;
}

// ---------------- 3) score GEMM via mma.sync ---------------------------------
// CTA: 256 t x 128 u, 512 threads (16 warps of 64x32). K = 17 chunks of 64.
// Stage: A 32KB | Bhi 16KB | Blo 16KB = 64KB. 3 stages.
#define STG      65536
#define OFF_MBAR 196608
#define OFF_QP   196672
#define OFF_VW   197184
#define OFF_RED  197696
#define SMEM_TOTAL 201792

__device__ __forceinline__ void issue_chunk(uint32_t sb, int s, int c,
                                            int b, int t0, int u0) {
    uint32_t mbar = sb + OFF_MBAR + s * 8;
    MBARRIER_EXPECT_TX(mbar, 65536u);
    bulk_g2s(sb + s * STG,
             (const void*)(g_vpk + ((size_t)((b * NCH + c) * 2048 + t0) * 8)),
             32768u, mbar);
    bulk_g2s(sb + s * STG + 32768,
             (const void*)(g_wpk + ((size_t)((c * 2 + 0) * U_ + u0) * 8)),
             16384u, mbar);
    bulk_g2s(sb + s * STG + 49152,
             (const void*)(g_wpk + ((size_t)((c * 2 + 1) * U_ + u0) * 8)),
             16384u, mbar);
}

__global__ __launch_bounds__(512, 1)
void score_mma_kernel(const float* __restrict__ Vw) {
    extern __shared__ char smem[];
    const uint32_t sb = smem_to_u32(smem);
    const int tid  = threadIdx.x;
    const int lane = tid & 31;
    const int wid  = tid >> 5;
    const int ut = blockIdx.x;          // 0..7 (fastest -> A L2 reuse)
    const int b  = blockIdx.y;          // 0..31
    const int tt = blockIdx.z;          // 0..7
    const int t0 = tt * 256, u0 = ut * 128;

    if (tid == 0) {
#pragma unroll
        for (int s = 0; s < 3; s++) MBARRIER_INIT(sb + OFF_MBAR + s * 8, 1);
    }
    __syncthreads();
    if (tid == 0) {
        for (int c = 0; c < 3; c++) issue_chunk(sb, c, c, b, t0, u0);
    }

    float* qp = (float*)(smem + OFF_QP);
    float* vw = (float*)(smem + OFF_VW);
    if (tid < 128)       qp[tid] = g_qproj[b * U_ + u0 + tid];
    else if (tid < 256)  vw[tid - 128] = __ldg(Vw + u0 + tid - 128);

    float acc[16][4];
#pragma unroll
    for (int i = 0; i < 16; i++)
#pragma unroll
        for (int j = 0; j < 4; j++) acc[i][j] = 0.f;

    const int wm = wid & 3;             // t block (rows wm*64..+63)
    const int wn = wid >> 2;            // u block (cols wn*32..+31)
    const int rowA = lane & 15;
    const int ka   = lane >> 4;
    const int rowB = (lane & 7) | ((lane >> 4) << 3);
    const int kb   = (lane >> 3) & 1;
    const uint32_t aOff  = (uint32_t)((wm * 64 + rowA) * 128);
    const uint32_t bhOff = (uint32_t)(32768 + (wn * 32 + rowB) * 128);
    const uint32_t blOff = (uint32_t)(49152 + (wn * 32 + rowB) * 128);

    int s = 0, par = 0;
    for (int c = 0; c < NCH; c++) {
        MBARRIER_WAIT_PARITY(sb + OFF_MBAR + s * 8, par);
        const uint32_t stg = sb + s * STG;
        const uint32_t aB  = stg + aOff;
        const uint32_t bhB = stg + bhOff;
        const uint32_t blB = stg + blOff;
#pragma unroll
        for (int ks = 0; ks < 4; ks++) {
            const int gA = ks * 2 + ka;
            const int gB = ks * 2 + kb;
            const uint32_t swA = (uint32_t)((gA ^ (rowA & 7)) << 4);
            const uint32_t swB = (uint32_t)((gB ^ (rowB & 7)) << 4);

            uint32_t ah[4][4], bh[4][2], bl[4][2], tmp[4];
#pragma unroll
            for (int mt = 0; mt < 4; mt++) ldsm4(ah[mt], aB + mt * 2048 + swA);
            ldsm4(tmp, bhB + swB);
            bh[0][0] = tmp[0]; bh[0][1] = tmp[1]; bh[1][0] = tmp[2]; bh[1][1] = tmp[3];
            ldsm4(tmp, bhB + 2048 + swB);
            bh[2][0] = tmp[0]; bh[2][1] = tmp[1]; bh[3][0] = tmp[2]; bh[3][1] = tmp[3];
            ldsm4(tmp, blB + swB);
            bl[0][0] = tmp[0]; bl[0][1] = tmp[1]; bl[1][0] = tmp[2]; bl[1][1] = tmp[3];
            ldsm4(tmp, blB + 2048 + swB);
            bl[2][0] = tmp[0]; bl[2][1] = tmp[1]; bl[3][0] = tmp[2]; bl[3][1] = tmp[3];
#pragma unroll
            for (int mt = 0; mt < 4; mt++)
#pragma unroll
                for (int nt = 0; nt < 4; nt++)
                    mma16816(acc[mt * 4 + nt], ah[mt], bh[nt]);
#pragma unroll
            for (int mt = 0; mt < 4; mt++)
#pragma unroll
                for (int nt = 0; nt < 4; nt++)
                    mma16816(acc[mt * 4 + nt], ah[mt], bl[nt]);
        }
        __syncthreads();
        if (tid == 0 && c + 3 < NCH) issue_chunk(sb, s, c + 3, b, t0, u0);
        if (++s == 3) { s = 0; par ^= 1; }
    }

    // epilogue: s = acc + qp[u]; rowsum += vw[u] * tanh(s)
    float rs[4][2];
#pragma unroll
    for (int mt = 0; mt < 4; mt++) { rs[mt][0] = 0.f; rs[mt][1] = 0.f; }
#pragma unroll
    for (int mt = 0; mt < 4; mt++) {
#pragma unroll
        for (int nt = 0; nt < 4; nt++) {
            int uc = wn * 32 + nt * 8 + ((lane & 3) << 1);
            float q0 = qp[uc], q1 = qp[uc + 1];
            float v0 = vw[uc], v1 = vw[uc + 1];
            float* a = acc[mt * 4 + nt];
            rs[mt][0] += v0 * tanhf(a[0] + q0) + v1 * tanhf(a[1] + q1);
            rs[mt][1] += v0 * tanhf(a[2] + q0) + v1 * tanhf(a[3] + q1);
        }
#pragma unroll
        for (int off = 1; off <= 2; off <<= 1) {
            rs[mt][0] += __shfl_xor_sync(0xffffffffu, rs[mt][0], off);
            rs[mt][1] += __shfl_xor_sync(0xffffffffu, rs[mt][1], off);
        }
    }
    float* red = (float*)(smem + OFF_RED);
    if ((lane & 3) == 0) {
#pragma unroll
        for (int mt = 0; mt < 4; mt++) {
            int r = wm * 64 + mt * 16 + (lane >> 2);
            red[wn * 256 + r]     = rs[mt][0];
            red[wn * 256 + r + 8] = rs[mt][1];
        }
    }
    __syncthreads();
    if (tid < 256) {
        float sv = red[tid] + red[256 + tid] + red[512 + tid] + red[768 + tid];
        g_part[(size_t)ut * (B_ * T_) + b * T_ + t0 + tid] = sv;
    }
}

// ---------------- 4) combine + softmax ---------------------------------------
__global__ void softmax_kernel(const float* __restrict__ Vb,
                               float* __restrict__ score,
                               float* __restrict__ att) {
    int b = blockIdx.x;
    int tid = threadIdx.x;  // 256
    __shared__ float sm[256];
    const float vb = __ldg(Vb);

    float v[8];
    float m = -3.402823466e38f;
#pragma unroll
    for (int i = 0; i < 8; i++) {
        int t = tid + i * 256;
        float s = vb;
#pragma unroll
        for (int z = 0; z < 8; z++) s += g_part[(size_t)z * (B_ * T_) + b * T_ + t];
        v[i] = s;
        score[(size_t)b * T_ + t] = s;
        m = fmaxf(m, s);
    }
    sm[tid] = m;
    __syncthreads();
    for (int off = 128; off > 0; off >>= 1) {
        if (tid < off) sm[tid] = fmaxf(sm[tid], sm[tid + off]);
        __syncthreads();
    }
    float M = sm[0];
    __syncthreads();

    float acc = 0.f;
#pragma unroll
    for (int i = 0; i < 8; i++) { v[i] = expf(v[i] - M); acc += v[i]; }
    sm[tid] = acc;
    __syncthreads();
    for (int off = 128; off > 0; off >>= 1) {
        if (tid < off) sm[tid] += sm[tid + off];
        __syncthreads();
    }
    float inv = 1.0f / sm[0];
#pragma unroll
    for (int i = 0; i < 8; i++)
        att[(size_t)b * T_ + tid + i * 256] = v[i] * inv;
}

// ---------------- 5) context (reads packed fp16 values) -----------------------
__global__ void ctx_partial_kernel(const float* __restrict__ att) {
    int b   = blockIdx.y;
    int sp  = blockIdx.z;              // 0..7, 256 t each
    int tid = threadIdx.x;             // 256
    int h   = blockIdx.x * 256 + tid;  // 0..1023
    int c   = h >> 6;
    int g   = (h >> 3) & 7;
    int e   = h & 7;
    __shared__ float a[256];
    int t0 = sp * 256;
    a[tid] = att[(size_t)b * T_ + t0 + tid];
    __syncthreads();
    const uint4* base = g_vpk + ((size_t)((b * NCH + c) * 2048 + t0) * 8);
    float acc = 0.f;
#pragma unroll 8
    for (int t = 0; t < 256; t++) {
        const __half* p = (const __half*)(base + (size_t)t * 8 + (g ^ (t & 7)));
        acc += a[t] * __half2float(p[e]);
    }
    g_ctx_partial[((size_t)b * 8 + sp) * H_ + h] = acc;
}

__global__ void ctx_reduce_kernel(float* __restrict__ ctx) {
    int idx = blockIdx.x * 256 + threadIdx.x;
    int b = idx >> 10;
    int h = idx & (H_ - 1);
    float s = 0.f;
#pragma unroll
    for (int sp = 0; sp < 8; sp++)
        s += g_ctx_partial[((size_t)b * 8 + sp) * H_ + h];
    ctx[idx] = s;
}

// ---------------- launch ------------------------------------------------------
extern "C" void kernel_launch(void* const* d_in, const int* in_sizes, int n_in,
                              void* d_out, int out_size) {
    const float* query    = (const float*)d_in[0];
    const float* values   = (const float*)d_in[1];
    const float* prev_att = (const float*)d_in[2];
    const float* W1w      = (const float*)d_in[3];
    const float* W1b      = (const float*)d_in[4];
    const float* W2w      = (const float*)d_in[5];
    const float* W2b      = (const float*)d_in[6];
    const float* Vw       = (const float*)d_in[7];
    const float* Vb       = (const float*)d_in[8];
    const float* conv_w   = (const float*)d_in[9];
    const float* LPw      = (const float*)d_in[10];

    float* out   = (float*)d_out;
    float* ctx   = out;
    float* att   = out + B_ * H_;
    float* score = out + B_ * H_ + B_ * T_;

    cudaFuncSetAttribute(score_mma_kernel,
                         cudaFuncAttributeMaxDynamicSharedMemorySize, SMEM_TOTAL);

    qproj_kernel<<<(B_ * U_ * 32 + 255) / 256, 256>>>(query, W2w, W1b, W2b);
    pack_w_kernel<<<(16 * U_) / 256, 256>>>(W1w);
    pack_lp_kernel<<<U_ / 256, 256>>>(LPw);
    pack_values_kernel<<<(B_ * 16 * T_) / 256, 256>>>(values);
    {
        dim3 g(T_ / 256, B_);
        loc_pack_kernel<<<g, 256>>>(prev_att, conv_w);
    }
    {
        dim3 g(8, B_, 8);   // x = u-tile (fastest), y = b, z = t-tile
        score_mma_kernel<<<g, 512, SMEM_TOTAL>>>(Vw);
    }
    softmax_kernel<<<B_, 256>>>(Vb, score, att);
    {
        dim3 g(4, B_, 8);
        ctx_partial_kernel<<<g, 256>>>(att);
        ctx_reduce_kernel<<<B_ * H_ / 256, 256>>>(ctx);
    }
}

// round 5
// speedup vs baseline: 6.0377x; 1.4228x over previous
#include <cuda_runtime.h>
#include <cuda_fp16.h>
#include <cstdint>
#include <math.h>

// ----------------------------------------------------------------------------
// BahdanauAttentionAudio — HMMA fp16 single-term score GEMM
//   B=32, T=2048, H=1024, U=1024, KN=32
// Output layout: [ ctx (32*1024) | att (32*2048) | score (32*2048) ]
// ----------------------------------------------------------------------------

#define B_   32
#define T_   2048
#define H_   1024
#define U_   1024
#define KN_  32
#define TAPS 31
#define NCH  17            // 16 chunks of H (K=64) + 1 loc chunk (K=32 pad 64)

// packed format: per (chunk c, row r): 128 bytes = 64 fp16 (k = c*64 .. +63)
// granule g (8 fp16 = 16B) stored at byte offset ((g ^ (r & 7)) * 16)
__device__ __align__(128) uint4 g_vpk[(size_t)B_ * NCH * T_ * 8];   // [b][c][t][8]
__device__ __align__(128) uint4 g_wpk[(size_t)NCH * U_ * 8];        // [c][u][8]
__device__ __align__(16)  float g_qproj[B_ * U_];
__device__ __align__(16)  float g_part[8 * B_ * T_];
__device__ __align__(16)  float g_ctx_partial[B_ * 8 * H_];

// ---------------- helpers ----------------------------------------------------
__device__ __forceinline__ uint32_t smem_to_u32(const void* p) {
    uint32_t a;
    asm("{ .reg .u64 t; cvta.to.shared.u64 t, %1; cvt.u32.u64 %0, t; }"
        : "=r"(a) : "l"(p));
    return a;
}

__device__ __forceinline__ uint32_t pkh(float a, float b) {
    __half2 h = __floats2half2_rn(a, b);
    return *reinterpret_cast<uint32_t*>(&h);
}

__device__ __forceinline__ uint4 pk8(const float* f) {
    uint4 r;
    r.x = pkh(f[0], f[1]); r.y = pkh(f[2], f[3]);
    r.z = pkh(f[4], f[5]); r.w = pkh(f[6], f[7]);
    return r;
}

#define MBARRIER_INIT(m, c) \
    asm volatile("mbarrier.init.shared.b64 [%0], %1;" \
                 :: "r"((uint32_t)(m)), "r"((uint32_t)(c)) : "memory")
#define MBARRIER_EXPECT_TX(m, n) \
    asm volatile("mbarrier.arrive.expect_tx.shared.b64 _, [%0], %1;" \
                 :: "r"((uint32_t)(m)), "r"((uint32_t)(n)) : "memory")

#define MBARRIER_WAIT_PARITY(mb, pp) do {                                     \
    uint32_t _m = (uint32_t)(mb), _p = (uint32_t)(pp), _d;                    \
    asm volatile(                                                             \
        "{\n\t.reg .pred p;\n\t"                                              \
        "mbarrier.try_wait.parity.acquire.cta.shared::cta.b64 p, [%1], %2;\n\t" \
        "selp.b32 %0, 1, 0, p;\n\t}"                                          \
        : "=r"(_d) : "r"(_m), "r"(_p) : "memory");                            \
    if (!_d) {                                                                \
        asm volatile(                                                         \
            "{\n\t.reg .pred P1;\n\t"                                         \
            "WL_%=:\n\t"                                                      \
            "mbarrier.try_wait.parity.acquire.cta.shared::cta.b64 P1, [%0], %1, 0x989680;\n\t" \
            "@P1 bra.uni WD_%=;\n\t"                                          \
            "bra.uni WL_%=;\n\t"                                              \
            "WD_%=:\n\t}"                                                     \
            :: "r"(_m), "r"(_p) : "memory");                                  \
    }                                                                         \
} while (0)

__device__ __forceinline__ void bulk_g2s(uint32_t dst, const void* src,
                                         uint32_t bytes, uint32_t mbar) {
    asm volatile(
        "cp.async.bulk.shared::cluster.global.mbarrier::complete_tx::bytes "
        "[%0], [%1], %2, [%3];"
        :: "r"(dst), "l"(src), "r"(bytes), "r"(mbar) : "memory");
}

__device__ __forceinline__ void ldsm4(uint32_t (&r)[4], uint32_t a) {
    asm volatile("ldmatrix.sync.aligned.m8n8.x4.shared.b16 {%0,%1,%2,%3}, [%4];"
                 : "=r"(r[0]), "=r"(r[1]), "=r"(r[2]), "=r"(r[3]) : "r"(a));
}

__device__ __forceinline__ void mma16816(float* c, const uint32_t* a,
                                         const uint32_t* b) {
    asm volatile(
        "mma.sync.aligned.m16n8k16.row.col.f32.f16.f16.f32 "
        "{%0,%1,%2,%3}, {%4,%5,%6,%7}, {%8,%9}, {%0,%1,%2,%3};"
        : "+f"(c[0]), "+f"(c[1]), "+f"(c[2]), "+f"(c[3])
        : "r"(a[0]), "r"(a[1]), "r"(a[2]), "r"(a[3]), "r"(b[0]), "r"(b[1]));
}

// ---------------- 1) query projection ---------------------------------------
__global__ void qproj_kernel(const float* __restrict__ query,
                             const float* __restrict__ W2w,
                             const float* __restrict__ W1b,
                             const float* __restrict__ W2b) {
    int gw   = (blockIdx.x * blockDim.x + threadIdx.x) >> 5;
    int lane = threadIdx.x & 31;
    if (gw >= B_ * U_) return;
    int u = gw & (U_ - 1);
    int b = gw >> 10;
    const float* qrow = query + (size_t)b * H_;
    const float* wrow = W2w + (size_t)u * H_;
    float acc = 0.f;
#pragma unroll 4
    for (int h = lane; h < H_; h += 32) acc += qrow[h] * wrow[h];
#pragma unroll
    for (int off = 16; off > 0; off >>= 1)
        acc += __shfl_xor_sync(0xffffffffu, acc, off);
    if (lane == 0) g_qproj[(size_t)b * U_ + u] = acc + W1b[u] + W2b[u];
}

// ---------------- 2a) pack values (fp16) --------------------------------------
__global__ void pack_values_kernel(const float* __restrict__ values) {
    int idx = blockIdx.x * 256 + threadIdx.x;   // (b*16 + c)*2048 + t
    int t  = idx & 2047;
    int bc = idx >> 11;
    int c  = bc & 15;
    int b  = bc >> 4;
    const float4* src = (const float4*)(values + ((size_t)(b * 2048 + t) * 1024 + c * 64));
    uint4* dst = g_vpk + ((size_t)((b * NCH + c) * 2048 + t) * 8);
    int r = t & 7;
    float f[8];
#pragma unroll
    for (int g = 0; g < 8; g++) {
        float4 v0 = __ldg(src + g * 2), v1 = __ldg(src + g * 2 + 1);
        f[0] = v0.x; f[1] = v0.y; f[2] = v0.z; f[3] = v0.w;
        f[4] = v1.x; f[5] = v1.y; f[6] = v1.z; f[7] = v1.w;
        dst[g ^ r] = pk8(f);
    }
}

// ---------------- 2b) pack W1_w (fp16) ----------------------------------------
__global__ void pack_w_kernel(const float* __restrict__ W1w) {
    int idx = blockIdx.x * 256 + threadIdx.x;   // c*1024 + u  (c 0..15)
    int u = idx & 1023;
    int c = idx >> 10;
    const float4* src = (const float4*)(W1w + ((size_t)u * 1024 + c * 64));
    uint4* dst = g_wpk + ((size_t)(c * U_ + u) * 8);
    int r = u & 7;
    float f[8];
#pragma unroll
    for (int g = 0; g < 8; g++) {
        float4 v0 = __ldg(src + g * 2), v1 = __ldg(src + g * 2 + 1);
        f[0] = v0.x; f[1] = v0.y; f[2] = v0.z; f[3] = v0.w;
        f[4] = v1.x; f[5] = v1.y; f[6] = v1.z; f[7] = v1.w;
        dst[g ^ r] = pk8(f);
    }
}

// ---------------- 2c) pack loc_proj_w (chunk 16 of W) -------------------------
__global__ void pack_lp_kernel(const float* __restrict__ LPw) {
    int u = blockIdx.x * 256 + threadIdx.x;     // 0..1023
    const float4* src = (const float4*)(LPw + (size_t)u * 32);
    uint4* dst = g_wpk + ((size_t)(16 * U_ + u) * 8);
    int r = u & 7;
    float f[8];
    uint4 z = make_uint4(0, 0, 0, 0);
#pragma unroll
    for (int g = 0; g < 4; g++) {
        float4 v0 = __ldg(src + g * 2), v1 = __ldg(src + g * 2 + 1);
        f[0] = v0.x; f[1] = v0.y; f[2] = v0.z; f[3] = v0.w;
        f[4] = v1.x; f[5] = v1.y; f[6] = v1.z; f[7] = v1.w;
        dst[g ^ r] = pk8(f);
    }
#pragma unroll
    for (int g = 4; g < 8; g++) dst[g ^ r] = z;
}

// ---------------- 2d) location conv + pack (chunk 16 of V) --------------------
__global__ void loc_pack_kernel(const float* __restrict__ prev_att,
                                const float* __restrict__ conv_w) {
    int b  = blockIdx.y;
    int t0 = blockIdx.x * 256;
    int tid = threadIdx.x;
    __shared__ float pa[256 + TAPS - 1];
    __shared__ float w[KN_][TAPS];
    for (int i = tid; i < 256 + TAPS - 1; i += 256) {
        int t = t0 - (TAPS / 2) + i;
        pa[i] = (t >= 0 && t < T_) ? prev_att[(size_t)b * T_ + t] : 0.f;
    }
    for (int i = tid; i < KN_ * TAPS; i += 256) w[i / TAPS][i % TAPS] = conv_w[i];
    __syncthreads();
    int t = t0 + tid;
    float a[KN_];
#pragma unroll 4
    for (int k = 0; k < KN_; k++) {
        float s = 0.f;
#pragma unroll
        for (int j = 0; j < TAPS; j++) s += w[k][j] * pa[tid + j];
        a[k] = s;
    }
    uint4* dst = g_vpk + ((size_t)((b * NCH + 16) * 2048 + t) * 8);
    int r = t & 7;
    uint4 z = make_uint4(0, 0, 0, 0);
#pragma unroll
    for (int g = 0; g < 4; g++) dst[g ^ r] = pk8(a + g * 8);
#pragma unroll
    for (int g = 4; g < 8; g++) dst[g ^ r] = z;
}

// ---------------- 3) score GEMM via mma.sync ---------------------------------
// CTA: 256 t x 128 u, 512 threads (16 warps of 64x32). K = 17 chunks of 64.
// Stage: A 32KB | B 16KB = 48KB. 4 stages.
#define STG      49152
#define OFF_MBAR 196608
#define OFF_QP   196672
#define OFF_VW   197184
#define OFF_RED  197696
#define SMEM_TOTAL 201792

__device__ __forceinline__ void issue_chunk(uint32_t sb, int s, int c,
                                            int b, int t0, int u0) {
    uint32_t mbar = sb + OFF_MBAR + s * 8;
    MBARRIER_EXPECT_TX(mbar, 49152u);
    bulk_g2s(sb + s * STG,
             (const void*)(g_vpk + ((size_t)((b * NCH + c) * 2048 + t0) * 8)),
             32768u, mbar);
    bulk_g2s(sb + s * STG + 32768,
             (const void*)(g_wpk + ((size_t)(c * U_ + u0) * 8)),
             16384u, mbar);
}

__global__ __launch_bounds__(512, 1)
void score_mma_kernel(const float* __restrict__ Vw) {
    extern __shared__ char smem[];
    const uint32_t sb = smem_to_u32(smem);
    const int tid  = threadIdx.x;
    const int lane = tid & 31;
    const int wid  = tid >> 5;
    const int ut = blockIdx.x;          // 0..7 (fastest -> A L2 reuse)
    const int b  = blockIdx.y;          // 0..31
    const int tt = blockIdx.z;          // 0..7
    const int t0 = tt * 256, u0 = ut * 128;

    if (tid == 0) {
#pragma unroll
        for (int s = 0; s < 4; s++) MBARRIER_INIT(sb + OFF_MBAR + s * 8, 1);
    }
    __syncthreads();
    if (tid == 0) {
        for (int c = 0; c < 4; c++) issue_chunk(sb, c, c, b, t0, u0);
    }

    float* qp = (float*)(smem + OFF_QP);
    float* vw = (float*)(smem + OFF_VW);
    if (tid < 128)       qp[tid] = g_qproj[b * U_ + u0 + tid];
    else if (tid < 256)  vw[tid - 128] = __ldg(Vw + u0 + tid - 128);

    float acc[16][4];
#pragma unroll
    for (int i = 0; i < 16; i++)
#pragma unroll
        for (int j = 0; j < 4; j++) acc[i][j] = 0.f;

    const int wm = wid & 3;             // t block (rows wm*64..+63)
    const int wn = wid >> 2;            // u block (cols wn*32..+31)
    const int rowA = lane & 15;
    const int ka   = lane >> 4;
    const int rowB = (lane & 7) | ((lane >> 4) << 3);
    const int kb   = (lane >> 3) & 1;
    const uint32_t aOff = (uint32_t)((wm * 64 + rowA) * 128);
    const uint32_t bOff = (uint32_t)(32768 + (wn * 32 + rowB) * 128);

    for (int c = 0; c < NCH; c++) {
        const int s = c & 3;
        MBARRIER_WAIT_PARITY(sb + OFF_MBAR + s * 8, (c >> 2) & 1);
        const uint32_t stg = sb + s * STG;
        const uint32_t aB = stg + aOff;
        const uint32_t bB = stg + bOff;
#pragma unroll
        for (int ks = 0; ks < 4; ks++) {
            const int gA = ks * 2 + ka;
            const int gB = ks * 2 + kb;
            const uint32_t swA = (uint32_t)((gA ^ (rowA & 7)) << 4);
            const uint32_t swB = (uint32_t)((gB ^ (rowB & 7)) << 4);

            uint32_t ah[4][4], bh[4][2], tmp[4];
#pragma unroll
            for (int mt = 0; mt < 4; mt++) ldsm4(ah[mt], aB + mt * 2048 + swA);
            ldsm4(tmp, bB + swB);
            bh[0][0] = tmp[0]; bh[0][1] = tmp[1]; bh[1][0] = tmp[2]; bh[1][1] = tmp[3];
            ldsm4(tmp, bB + 2048 + swB);
            bh[2][0] = tmp[0]; bh[2][1] = tmp[1]; bh[3][0] = tmp[2]; bh[3][1] = tmp[3];
#pragma unroll
            for (int mt = 0; mt < 4; mt++)
#pragma unroll
                for (int nt = 0; nt < 4; nt++)
                    mma16816(acc[mt * 4 + nt], ah[mt], bh[nt]);
        }
        __syncthreads();
        if (tid == 0 && c + 4 < NCH) issue_chunk(sb, s, c + 4, b, t0, u0);
    }

    // epilogue: s = acc + qp[u]; rowsum += vw[u] * tanh(s)
    float rs[4][2];
#pragma unroll
    for (int mt = 0; mt < 4; mt++) { rs[mt][0] = 0.f; rs[mt][1] = 0.f; }
#pragma unroll
    for (int mt = 0; mt < 4; mt++) {
#pragma unroll
        for (int nt = 0; nt < 4; nt++) {
            int uc = wn * 32 + nt * 8 + ((lane & 3) << 1);
            float q0 = qp[uc], q1 = qp[uc + 1];
            float v0 = vw[uc], v1 = vw[uc + 1];
            float* a = acc[mt * 4 + nt];
            rs[mt][0] += v0 * tanhf(a[0] + q0) + v1 * tanhf(a[1] + q1);
            rs[mt][1] += v0 * tanhf(a[2] + q0) + v1 * tanhf(a[3] + q1);
        }
#pragma unroll
        for (int off = 1; off <= 2; off <<= 1) {
            rs[mt][0] += __shfl_xor_sync(0xffffffffu, rs[mt][0], off);
            rs[mt][1] += __shfl_xor_sync(0xffffffffu, rs[mt][1], off);
        }
    }
    float* red = (float*)(smem + OFF_RED);
    if ((lane & 3) == 0) {
#pragma unroll
        for (int mt = 0; mt < 4; mt++) {
            int r = wm * 64 + mt * 16 + (lane >> 2);
            red[wn * 256 + r]     = rs[mt][0];
            red[wn * 256 + r + 8] = rs[mt][1];
        }
    }
    __syncthreads();
    if (tid < 256) {
        float sv = red[tid] + red[256 + tid] + red[512 + tid] + red[768 + tid];
        g_part[(size_t)ut * (B_ * T_) + b * T_ + t0 + tid] = sv;
    }
}

// ---------------- 4) combine + softmax ---------------------------------------
__global__ void softmax_kernel(const float* __restrict__ Vb,
                               float* __restrict__ score,
                               float* __restrict__ att) {
    int b = blockIdx.x;
    int tid = threadIdx.x;  // 256
    __shared__ float sm[256];
    const float vb = __ldg(Vb);

    float v[8];
    float m = -3.402823466e38f;
#pragma unroll
    for (int i = 0; i < 8; i++) {
        int t = tid + i * 256;
        float s = vb;
#pragma unroll
        for (int z = 0; z < 8; z++) s += g_part[(size_t)z * (B_ * T_) + b * T_ + t];
        v[i] = s;
        score[(size_t)b * T_ + t] = s;
        m = fmaxf(m, s);
    }
    sm[tid] = m;
    __syncthreads();
    for (int off = 128; off > 0; off >>= 1) {
        if (tid < off) sm[tid] = fmaxf(sm[tid], sm[tid + off]);
        __syncthreads();
    }
    float M = sm[0];
    __syncthreads();

    float acc = 0.f;
#pragma unroll
    for (int i = 0; i < 8; i++) { v[i] = expf(v[i] - M); acc += v[i]; }
    sm[tid] = acc;
    __syncthreads();
    for (int off = 128; off > 0; off >>= 1) {
        if (tid < off) sm[tid] += sm[tid + off];
        __syncthreads();
    }
    float inv = 1.0f / sm[0];
#pragma unroll
    for (int i = 0; i < 8; i++)
        att[(size_t)b * T_ + tid + i * 256] = v[i] * inv;
}

// ---------------- 5) context (reads packed fp16 values) -----------------------
__global__ void ctx_partial_kernel(const float* __restrict__ att) {
    int b   = blockIdx.y;
    int sp  = blockIdx.z;              // 0..7, 256 t each
    int tid = threadIdx.x;             // 256
    int h   = blockIdx.x * 256 + tid;  // 0..1023
    int c   = h >> 6;
    int g   = (h >> 3) & 7;
    int e   = h & 7;
    __shared__ float a[256];
    int t0 = sp * 256;
    a[tid] = att[(size_t)b * T_ + t0 + tid];
    __syncthreads();
    const uint4* base = g_vpk + ((size_t)((b * NCH + c) * 2048 + t0) * 8);
    float acc = 0.f;
#pragma unroll 8
    for (int t = 0; t < 256; t++) {
        const __half* p = (const __half*)(base + (size_t)t * 8 + (g ^ (t & 7)));
        acc += a[t] * __half2float(p[e]);
    }
    g_ctx_partial[((size_t)b * 8 + sp) * H_ + h] = acc;
}

__global__ void ctx_reduce_kernel(float* __restrict__ ctx) {
    int idx = blockIdx.x * 256 + threadIdx.x;
    int b = idx >> 10;
    int h = idx & (H_ - 1);
    float s = 0.f;
#pragma unroll
    for (int sp = 0; sp < 8; sp++)
        s += g_ctx_partial[((size_t)b * 8 + sp) * H_ + h];
    ctx[idx] = s;
}

// ---------------- launch ------------------------------------------------------
extern "C" void kernel_launch(void* const* d_in, const int* in_sizes, int n_in,
                              void* d_out, int out_size) {
    const float* query    = (const float*)d_in[0];
    const float* values   = (const float*)d_in[1];
    const float* prev_att = (const float*)d_in[2];
    const float* W1w      = (const float*)d_in[3];
    const float* W1b      = (const float*)d_in[4];
    const float* W2w      = (const float*)d_in[5];
    const float* W2b      = (const float*)d_in[6];
    const float* Vw       = (const float*)d_in[7];
    const float* Vb       = (const float*)d_in[8];
    const float* conv_w   = (const float*)d_in[9];
    const float* LPw      = (const float*)d_in[10];

    float* out   = (float*)d_out;
    float* ctx   = out;
    float* att   = out + B_ * H_;
    float* score = out + B_ * H_ + B_ * T_;

    cudaFuncSetAttribute(score_mma_kernel,
                         cudaFuncAttributeMaxDynamicSharedMemorySize, SMEM_TOTAL);

    qproj_kernel<<<(B_ * U_ * 32 + 255) / 256, 256>>>(query, W2w, W1b, W2b);
    pack_w_kernel<<<(16 * U_) / 256, 256>>>(W1w);
    pack_lp_kernel<<<U_ / 256, 256>>>(LPw);
    pack_values_kernel<<<(B_ * 16 * T_) / 256, 256>>>(values);
    {
        dim3 g(T_ / 256, B_);
        loc_pack_kernel<<<g, 256>>>(prev_att, conv_w);
    }
    {
        dim3 g(8, B_, 8);   // x = u-tile (fastest), y = b, z = t-tile
        score_mma_kernel<<<g, 512, SMEM_TOTAL>>>(Vw);
    }
    softmax_kernel<<<B_, 256>>>(Vb, score, att);
    {
        dim3 g(4, B_, 8);
        ctx_partial_kernel<<<g, 256>>>(att);
        ctx_reduce_kernel<<<B_ * H_ / 256, 256>>>(ctx);
    }
}

// round 6
// speedup vs baseline: 6.5603x; 1.0866x over previous
#include <cuda_runtime.h>
#include <cuda_fp16.h>
#include <cstdint>
#include <math.h>

// ----------------------------------------------------------------------------
// BahdanauAttentionAudio — HMMA fp16 single-term score GEMM
//   B=32, T=2048, H=1024, U=1024, KN=32
// Output layout: [ ctx (32*1024) | att (32*2048) | score (32*2048) ]
// ----------------------------------------------------------------------------

#define B_   32
#define T_   2048
#define H_   1024
#define U_   1024
#define KN_  32
#define TAPS 31
#define NCH  17            // 16 chunks of H (K=64) + 1 loc chunk (K=32 pad 64)

// packed format: per (chunk c, row r): 128 bytes = 64 fp16 (k = c*64 .. +63)
// granule g (8 fp16 = 16B) stored at byte offset ((g ^ (r & 7)) * 16)
__device__ __align__(128) uint4 g_vpk[(size_t)B_ * NCH * T_ * 8];   // [b][c][t][8]
__device__ __align__(128) uint4 g_wpk[(size_t)NCH * U_ * 8];        // [c][u][8]
__device__ __align__(16)  float g_qproj[B_ * U_];
__device__ __align__(16)  float g_part[8 * B_ * T_];
__device__ __align__(16)  float g_ctx_partial[B_ * 8 * H_];

// ---------------- helpers ----------------------------------------------------
__device__ __forceinline__ uint32_t smem_to_u32(const void* p) {
    uint32_t a;
    asm("{ .reg .u64 t; cvta.to.shared.u64 t, %1; cvt.u32.u64 %0, t; }"
        : "=r"(a) : "l"(p));
    return a;
}

__device__ __forceinline__ uint32_t pkh(float a, float b) {
    __half2 h = __floats2half2_rn(a, b);
    return *reinterpret_cast<uint32_t*>(&h);
}

__device__ __forceinline__ uint4 pk8(const float* f) {
    uint4 r;
    r.x = pkh(f[0], f[1]); r.y = pkh(f[2], f[3]);
    r.z = pkh(f[4], f[5]); r.w = pkh(f[6], f[7]);
    return r;
}

__device__ __forceinline__ float fast_tanh(float x) {
    // tanh(x) = (e^{2x}-1)/(e^{2x}+1), e^{2x} = 2^{2x*log2(e)}
    float xx = fminf(fmaxf(x, -15.f), 15.f) * 2.8853900817779268f;
    float e, r;
    asm("ex2.approx.f32 %0, %1;" : "=f"(e) : "f"(xx));
    float d = e + 1.f;
    asm("rcp.approx.f32 %0, %1;" : "=f"(r) : "f"(d));
    return (e - 1.f) * r;
}

#define MBARRIER_INIT(m, c) \
    asm volatile("mbarrier.init.shared.b64 [%0], %1;" \
                 :: "r"((uint32_t)(m)), "r"((uint32_t)(c)) : "memory")
#define MBARRIER_EXPECT_TX(m, n) \
    asm volatile("mbarrier.arrive.expect_tx.shared.b64 _, [%0], %1;" \
                 :: "r"((uint32_t)(m)), "r"((uint32_t)(n)) : "memory")

#define MBARRIER_WAIT_PARITY(mb, pp) do {                                     \
    uint32_t _m = (uint32_t)(mb), _p = (uint32_t)(pp), _d;                    \
    asm volatile(                                                             \
        "{\n\t.reg .pred p;\n\t"                                              \
        "mbarrier.try_wait.parity.acquire.cta.shared::cta.b64 p, [%1], %2;\n\t" \
        "selp.b32 %0, 1, 0, p;\n\t}"                                          \
        : "=r"(_d) : "r"(_m), "r"(_p) : "memory");                            \
    if (!_d) {                                                                \
        asm volatile(                                                         \
            "{\n\t.reg .pred P1;\n\t"                                         \
            "WL_%=:\n\t"                                                      \
            "mbarrier.try_wait.parity.acquire.cta.shared::cta.b64 P1, [%0], %1, 0x989680;\n\t" \
            "@P1 bra.uni WD_%=;\n\t"                                          \
            "bra.uni WL_%=;\n\t"                                              \
            "WD_%=:\n\t}"                                                     \
            :: "r"(_m), "r"(_p) : "memory");                                  \
    }                                                                         \
} while (0)

__device__ __forceinline__ void bulk_g2s(uint32_t dst, const void* src,
                                         uint32_t bytes, uint32_t mbar) {
    asm volatile(
        "cp.async.bulk.shared::cluster.global.mbarrier::complete_tx::bytes "
        "[%0], [%1], %2, [%3];"
        :: "r"(dst), "l"(src), "r"(bytes), "r"(mbar) : "memory");
}

__device__ __forceinline__ void ldsm4(uint32_t (&r)[4], uint32_t a) {
    asm volatile("ldmatrix.sync.aligned.m8n8.x4.shared.b16 {%0,%1,%2,%3}, [%4];"
                 : "=r"(r[0]), "=r"(r[1]), "=r"(r[2]), "=r"(r[3]) : "r"(a));
}

__device__ __forceinline__ void mma16816(float* c, const uint32_t* a,
                                         const uint32_t* b) {
    asm volatile(
        "mma.sync.aligned.m16n8k16.row.col.f32.f16.f16.f32 "
        "{%0,%1,%2,%3}, {%4,%5,%6,%7}, {%8,%9}, {%0,%1,%2,%3};"
        : "+f"(c[0]), "+f"(c[1]), "+f"(c[2]), "+f"(c[3])
        : "r"(a[0]), "r"(a[1]), "r"(a[2]), "r"(a[3]), "r"(b[0]), "r"(b[1]));
}

// ---------------- 1) query projection ---------------------------------------
__global__ void qproj_kernel(const float* __restrict__ query,
                             const float* __restrict__ W2w,
                             const float* __restrict__ W1b,
                             const float* __restrict__ W2b) {
    int gw   = (blockIdx.x * blockDim.x + threadIdx.x) >> 5;
    int lane = threadIdx.x & 31;
    if (gw >= B_ * U_) return;
    int u = gw & (U_ - 1);
    int b = gw >> 10;
    const float* qrow = query + (size_t)b * H_;
    const float* wrow = W2w + (size_t)u * H_;
    float acc = 0.f;
#pragma unroll 4
    for (int h = lane; h < H_; h += 32) acc += qrow[h] * wrow[h];
#pragma unroll
    for (int off = 16; off > 0; off >>= 1)
        acc += __shfl_xor_sync(0xffffffffu, acc, off);
    if (lane == 0) g_qproj[(size_t)b * U_ + u] = acc + W1b[u] + W2b[u];
}

// ---------------- 2a) pack values (fp16, coalesced granule-per-thread) -------
// idx -> g (inner), t, c, b. Lanes 0..7 cover one t-row's 8 granules:
// reads 256B contiguous fp32 per row-octet, writes one full 128B line.
__global__ void pack_values_kernel(const float* __restrict__ values) {
    int idx = blockIdx.x * 256 + threadIdx.x;
    int g = idx & 7;
    int t = (idx >> 3) & 2047;
    int c = (idx >> 14) & 15;
    int b = idx >> 18;
    const float4* src = (const float4*)(values +
        ((size_t)(b * 2048 + t) * 1024 + c * 64 + g * 8));
    float4 v0 = __ldg(src), v1 = __ldg(src + 1);
    float f[8] = {v0.x, v0.y, v0.z, v0.w, v1.x, v1.y, v1.z, v1.w};
    g_vpk[((size_t)((b * NCH + c) * 2048 + t) * 8) + (g ^ (t & 7))] = pk8(f);
}

// ---------------- 2b) pack W1_w (fp16) ----------------------------------------
__global__ void pack_w_kernel(const float* __restrict__ W1w) {
    int idx = blockIdx.x * 256 + threadIdx.x;   // c*1024 + u  (c 0..15)
    int u = idx & 1023;
    int c = idx >> 10;
    const float4* src = (const float4*)(W1w + ((size_t)u * 1024 + c * 64));
    uint4* dst = g_wpk + ((size_t)(c * U_ + u) * 8);
    int r = u & 7;
    float f[8];
#pragma unroll
    for (int g = 0; g < 8; g++) {
        float4 v0 = __ldg(src + g * 2), v1 = __ldg(src + g * 2 + 1);
        f[0] = v0.x; f[1] = v0.y; f[2] = v0.z; f[3] = v0.w;
        f[4] = v1.x; f[5] = v1.y; f[6] = v1.z; f[7] = v1.w;
        dst[g ^ r] = pk8(f);
    }
}

// ---------------- 2c) pack loc_proj_w (chunk 16 of W) -------------------------
__global__ void pack_lp_kernel(const float* __restrict__ LPw) {
    int u = blockIdx.x * 256 + threadIdx.x;     // 0..1023
    const float4* src = (const float4*)(LPw + (size_t)u * 32);
    uint4* dst = g_wpk + ((size_t)(16 * U_ + u) * 8);
    int r = u & 7;
    float f[8];
    uint4 z = make_uint4(0, 0, 0, 0);
#pragma unroll
    for (int g = 0; g < 4; g++) {
        float4 v0 = __ldg(src + g * 2), v1 = __ldg(src + g * 2 + 1);
        f[0] = v0.x; f[1] = v0.y; f[2] = v0.z; f[3] = v0.w;
        f[4] = v1.x; f[5] = v1.y; f[6] = v1.z; f[7] = v1.w;
        dst[g ^ r] = pk8(f);
    }
#pragma unroll
    for (int g = 4; g < 8; g++) dst[g ^ r] = z;
}

// ---------------- 2d) location conv + pack (chunk 16 of V) --------------------
__global__ void loc_pack_kernel(const float* __restrict__ prev_att,
                                const float* __restrict__ conv_w) {
    int b  = blockIdx.y;
    int t0 = blockIdx.x * 256;
    int tid = threadIdx.x;
    __shared__ float pa[256 + TAPS - 1];
    __shared__ float w[KN_][TAPS];
    for (int i = tid; i < 256 + TAPS - 1; i += 256) {
        int t = t0 - (TAPS / 2) + i;
        pa[i] = (t >= 0 && t < T_) ? prev_att[(size_t)b * T_ + t] : 0.f;
    }
    for (int i = tid; i < KN_ * TAPS; i += 256) w[i / TAPS][i % TAPS] = conv_w[i];
    __syncthreads();
    int t = t0 + tid;
    float a[KN_];
#pragma unroll 4
    for (int k = 0; k < KN_; k++) {
        float s = 0.f;
#pragma unroll
        for (int j = 0; j < TAPS; j++) s += w[k][j] * pa[tid + j];
        a[k] = s;
    }
    uint4* dst = g_vpk + ((size_t)((b * NCH + 16) * 2048 + t) * 8);
    int r = t & 7;
    uint4 z = make_uint4(0, 0, 0, 0);
#pragma unroll
    for (int g = 0; g < 4; g++) dst[g ^ r] = pk8(a + g * 8);
#pragma unroll
    for (int g = 4; g < 8; g++) dst[g ^ r] = z;
}

// ---------------- 3) score GEMM via mma.sync ---------------------------------
// CTA: 256 t x 128 u, 512 threads (16 warps of 64x32). K = 17 chunks of 64.
// Stage: A 32KB | B 16KB = 48KB. 4 stages.
#define STG      49152
#define OFF_MBAR 196608
#define OFF_QP   196672
#define OFF_VW   197184
#define OFF_RED  197696
#define SMEM_TOTAL 201792

__device__ __forceinline__ void issue_chunk(uint32_t sb, int s, int c,
                                            int b, int t0, int u0) {
    uint32_t mbar = sb + OFF_MBAR + s * 8;
    MBARRIER_EXPECT_TX(mbar, 49152u);
    bulk_g2s(sb + s * STG,
             (const void*)(g_vpk + ((size_t)((b * NCH + c) * 2048 + t0) * 8)),
             32768u, mbar);
    bulk_g2s(sb + s * STG + 32768,
             (const void*)(g_wpk + ((size_t)(c * U_ + u0) * 8)),
             16384u, mbar);
}

__global__ __launch_bounds__(512, 1)
void score_mma_kernel(const float* __restrict__ Vw) {
    extern __shared__ char smem[];
    const uint32_t sb = smem_to_u32(smem);
    const int tid  = threadIdx.x;
    const int lane = tid & 31;
    const int wid  = tid >> 5;
    const int ut = blockIdx.x;          // 0..7 (fastest -> A L2 reuse)
    const int b  = blockIdx.y;          // 0..31
    const int tt = blockIdx.z;          // 0..7
    const int t0 = tt * 256, u0 = ut * 128;

    if (tid == 0) {
#pragma unroll
        for (int s = 0; s < 4; s++) MBARRIER_INIT(sb + OFF_MBAR + s * 8, 1);
    }
    __syncthreads();
    if (tid == 0) {
        for (int c = 0; c < 4; c++) issue_chunk(sb, c, c, b, t0, u0);
    }

    float* qp = (float*)(smem + OFF_QP);
    float* vw = (float*)(smem + OFF_VW);
    if (tid < 128)       qp[tid] = g_qproj[b * U_ + u0 + tid];
    else if (tid < 256)  vw[tid - 128] = __ldg(Vw + u0 + tid - 128);

    float acc[16][4];
#pragma unroll
    for (int i = 0; i < 16; i++)
#pragma unroll
        for (int j = 0; j < 4; j++) acc[i][j] = 0.f;

    const int wm = wid & 3;             // t block (rows wm*64..+63)
    const int wn = wid >> 2;            // u block (cols wn*32..+31)
    const int rowA = lane & 15;
    const int ka   = lane >> 4;
    const int rowB = (lane & 7) | ((lane >> 4) << 3);
    const int kb   = (lane >> 3) & 1;
    const uint32_t aOff = (uint32_t)((wm * 64 + rowA) * 128);
    const uint32_t bOff = (uint32_t)(32768 + (wn * 32 + rowB) * 128);

    for (int c = 0; c < NCH; c++) {
        const int s = c & 3;
        MBARRIER_WAIT_PARITY(sb + OFF_MBAR + s * 8, (c >> 2) & 1);
        const uint32_t stg = sb + s * STG;
        const uint32_t aB = stg + aOff;
        const uint32_t bB = stg + bOff;
#pragma unroll
        for (int ks = 0; ks < 4; ks++) {
            const int gA = ks * 2 + ka;
            const int gB = ks * 2 + kb;
            const uint32_t swA = (uint32_t)((gA ^ (rowA & 7)) << 4);
            const uint32_t swB = (uint32_t)((gB ^ (rowB & 7)) << 4);

            uint32_t ah[4][4], bh[4][2], tmp[4];
#pragma unroll
            for (int mt = 0; mt < 4; mt++) ldsm4(ah[mt], aB + mt * 2048 + swA);
            ldsm4(tmp, bB + swB);
            bh[0][0] = tmp[0]; bh[0][1] = tmp[1]; bh[1][0] = tmp[2]; bh[1][1] = tmp[3];
            ldsm4(tmp, bB + 2048 + swB);
            bh[2][0] = tmp[0]; bh[2][1] = tmp[1]; bh[3][0] = tmp[2]; bh[3][1] = tmp[3];
#pragma unroll
            for (int mt = 0; mt < 4; mt++)
#pragma unroll
                for (int nt = 0; nt < 4; nt++)
                    mma16816(acc[mt * 4 + nt], ah[mt], bh[nt]);
        }
        __syncthreads();
        if (tid == 0 && c + 4 < NCH) issue_chunk(sb, s, c + 4, b, t0, u0);
    }

    // epilogue: s = acc + qp[u]; rowsum += vw[u] * tanh(s)
    float rs[4][2];
#pragma unroll
    for (int mt = 0; mt < 4; mt++) { rs[mt][0] = 0.f; rs[mt][1] = 0.f; }
#pragma unroll
    for (int mt = 0; mt < 4; mt++) {
#pragma unroll
        for (int nt = 0; nt < 4; nt++) {
            int uc = wn * 32 + nt * 8 + ((lane & 3) << 1);
            float q0 = qp[uc], q1 = qp[uc + 1];
            float v0 = vw[uc], v1 = vw[uc + 1];
            float* a = acc[mt * 4 + nt];
            rs[mt][0] += v0 * fast_tanh(a[0] + q0) + v1 * fast_tanh(a[1] + q1);
            rs[mt][1] += v0 * fast_tanh(a[2] + q0) + v1 * fast_tanh(a[3] + q1);
        }
#pragma unroll
        for (int off = 1; off <= 2; off <<= 1) {
            rs[mt][0] += __shfl_xor_sync(0xffffffffu, rs[mt][0], off);
            rs[mt][1] += __shfl_xor_sync(0xffffffffu, rs[mt][1], off);
        }
    }
    float* red = (float*)(smem + OFF_RED);
    if ((lane & 3) == 0) {
#pragma unroll
        for (int mt = 0; mt < 4; mt++) {
            int r = wm * 64 + mt * 16 + (lane >> 2);
            red[wn * 256 + r]     = rs[mt][0];
            red[wn * 256 + r + 8] = rs[mt][1];
        }
    }
    __syncthreads();
    if (tid < 256) {
        float sv = red[tid] + red[256 + tid] + red[512 + tid] + red[768 + tid];
        g_part[(size_t)ut * (B_ * T_) + b * T_ + t0 + tid] = sv;
    }
}

// ---------------- 4) combine + softmax ---------------------------------------
__global__ void softmax_kernel(const float* __restrict__ Vb,
                               float* __restrict__ score,
                               float* __restrict__ att) {
    int b = blockIdx.x;
    int tid = threadIdx.x;  // 256
    __shared__ float sm[256];
    const float vb = __ldg(Vb);

    float v[8];
    float m = -3.402823466e38f;
#pragma unroll
    for (int i = 0; i < 8; i++) {
        int t = tid + i * 256;
        float s = vb;
#pragma unroll
        for (int z = 0; z < 8; z++) s += g_part[(size_t)z * (B_ * T_) + b * T_ + t];
        v[i] = s;
        score[(size_t)b * T_ + t] = s;
        m = fmaxf(m, s);
    }
    sm[tid] = m;
    __syncthreads();
    for (int off = 128; off > 0; off >>= 1) {
        if (tid < off) sm[tid] = fmaxf(sm[tid], sm[tid + off]);
        __syncthreads();
    }
    float M = sm[0];
    __syncthreads();

    float acc = 0.f;
#pragma unroll
    for (int i = 0; i < 8; i++) { v[i] = expf(v[i] - M); acc += v[i]; }
    sm[tid] = acc;
    __syncthreads();
    for (int off = 128; off > 0; off >>= 1) {
        if (tid < off) sm[tid] += sm[tid + off];
        __syncthreads();
    }
    float inv = 1.0f / sm[0];
#pragma unroll
    for (int i = 0; i < 8; i++)
        att[(size_t)b * T_ + tid + i * 256] = v[i] * inv;
}

// ---------------- 5) context (reads packed fp16 values) -----------------------
__global__ void ctx_partial_kernel(const float* __restrict__ att) {
    int b   = blockIdx.y;
    int sp  = blockIdx.z;              // 0..7, 256 t each
    int tid = threadIdx.x;             // 256
    int h   = blockIdx.x * 256 + tid;  // 0..1023
    int c   = h >> 6;
    int g   = (h >> 3) & 7;
    int e   = h & 7;
    __shared__ float a[256];
    int t0 = sp * 256;
    a[tid] = att[(size_t)b * T_ + t0 + tid];
    __syncthreads();
    const uint4* base = g_vpk + ((size_t)((b * NCH + c) * 2048 + t0) * 8);
    float acc = 0.f;
#pragma unroll 8
    for (int t = 0; t < 256; t++) {
        const __half* p = (const __half*)(base + (size_t)t * 8 + (g ^ (t & 7)));
        acc += a[t] * __half2float(p[e]);
    }
    g_ctx_partial[((size_t)b * 8 + sp) * H_ + h] = acc;
}

__global__ void ctx_reduce_kernel(float* __restrict__ ctx) {
    int idx = blockIdx.x * 256 + threadIdx.x;
    int b = idx >> 10;
    int h = idx & (H_ - 1);
    float s = 0.f;
#pragma unroll
    for (int sp = 0; sp < 8; sp++)
        s += g_ctx_partial[((size_t)b * 8 + sp) * H_ + h];
    ctx[idx] = s;
}

// ---------------- launch ------------------------------------------------------
extern "C" void kernel_launch(void* const* d_in, const int* in_sizes, int n_in,
                              void* d_out, int out_size) {
    const float* query    = (const float*)d_in[0];
    const float* values   = (const float*)d_in[1];
    const float* prev_att = (const float*)d_in[2];
    const float* W1w      = (const float*)d_in[3];
    const float* W1b      = (const float*)d_in[4];
    const float* W2w      = (const float*)d_in[5];
    const float* W2b      = (const float*)d_in[6];
    const float* Vw       = (const float*)d_in[7];
    const float* Vb       = (const float*)d_in[8];
    const float* conv_w   = (const float*)d_in[9];
    const float* LPw      = (const float*)d_in[10];

    float* out   = (float*)d_out;
    float* ctx   = out;
    float* att   = out + B_ * H_;
    float* score = out + B_ * H_ + B_ * T_;

    cudaFuncSetAttribute(score_mma_kernel,
                         cudaFuncAttributeMaxDynamicSharedMemorySize, SMEM_TOTAL);

    qproj_kernel<<<(B_ * U_ * 32 + 255) / 256, 256>>>(query, W2w, W1b, W2b);
    pack_w_kernel<<<(16 * U_) / 256, 256>>>(W1w);
    pack_lp_kernel<<<U_ / 256, 256>>>(LPw);
    pack_values_kernel<<<(B_ * 16 * T_ * 8) / 256, 256>>>(values);
    {
        dim3 g(T_ / 256, B_);
        loc_pack_kernel<<<g, 256>>>(prev_att, conv_w);
    }
    {
        dim3 g(8, B_, 8);   // x = u-tile (fastest), y = b, z = t-tile
        score_mma_kernel<<<g, 512, SMEM_TOTAL>>>(Vw);
    }
    softmax_kernel<<<B_, 256>>>(Vb, score, att);
    {
        dim3 g(4, B_, 8);
        ctx_partial_kernel<<<g, 256>>>(att);
        ctx_reduce_kernel<<<B_ * H_ / 256, 256>>>(ctx);
    }
}